// round 1
// baseline (speedup 1.0000x reference)
#include <cuda_runtime.h>
#include <cstdint>

// Problem constants
#define SEQ   2048
#define BATCH 4
#define EMB   1024
#define HEADS 16
#define HDIM  64
#define NHEAD (BATCH*HEADS)     // 64
#define MROWS (SEQ*BATCH)       // 8192

// Scratch (device globals — no runtime allocation)
__device__ float g_q[(size_t)NHEAD * SEQ * HDIM];   // 32 MB, pre-scaled by D^-1/2
__device__ float g_k[(size_t)NHEAD * SEQ * HDIM];   // 32 MB
__device__ float g_v[(size_t)NHEAD * SEQ * HDIM];   // 32 MB
__device__ float g_ctx[(size_t)MROWS * EMB];        // 32 MB, (s,b,e) layout

// ---------------------------------------------------------------------------
// TF32 helpers
// ---------------------------------------------------------------------------
__device__ __forceinline__ uint32_t f2tf32(float x) {
    uint32_t y;
    asm("cvt.rna.tf32.f32 %0, %1;" : "=r"(y) : "f"(x));
    return y;
}

__device__ __forceinline__ void mma8(float* c, const uint32_t* a, const uint32_t* b) {
    asm volatile(
        "mma.sync.aligned.m16n8k8.row.col.f32.tf32.tf32.f32 "
        "{%0,%1,%2,%3}, {%4,%5,%6,%7}, {%8,%9}, {%0,%1,%2,%3};\n"
        : "+f"(c[0]), "+f"(c[1]), "+f"(c[2]), "+f"(c[3])
        : "r"(a[0]), "r"(a[1]), "r"(a[2]), "r"(a[3]), "r"(b[0]), "r"(b[1]));
}

// ---------------------------------------------------------------------------
// TF32 GEMM: C[M,N] = A[M,K] @ W[N,K]^T + bias
// Block 128x128, BK=32, 256 threads (8 warps, 2x4), warp tile 64x32.
// MODE 0: plain store to C.
// MODE 1: qkv scatter into g_q (scaled), g_k, g_v.
// ---------------------------------------------------------------------------
__device__ __forceinline__ void store_qkv(int m, int f, float v, const float* bias) {
    v += bias[f];
    int s = m >> 2;          // BATCH = 4
    int b = m & 3;
    int which = f >> 10;     // EMB = 1024
    int e = f & 1023;
    int h = e >> 6;          // HDIM = 64
    int d = e & 63;
    int idx = ((b * HEADS + h) * SEQ + s) * HDIM + d;
    if (which == 0)      g_q[idx] = v * 0.125f;   // 1/sqrt(64)
    else if (which == 1) g_k[idx] = v;
    else                 g_v[idx] = v;
}

template <int MODE>
__global__ void __launch_bounds__(256) gemm_tf32(
    const float* __restrict__ A, const float* __restrict__ W,
    const float* __restrict__ bias, float* __restrict__ C,
    int M, int N, int K)
{
    __shared__ uint32_t As[128][33];
    __shared__ uint32_t Bs[128][33];

    const int tid  = threadIdx.x;
    const int warp = tid >> 5;
    const int lane = tid & 31;
    const int gid  = lane >> 2;   // 0..7
    const int tig  = lane & 3;    // 0..3
    const int wm   = warp >> 2;   // 0..1
    const int wn   = warp & 3;    // 0..3

    const int bm = blockIdx.y * 128;
    const int bn = blockIdx.x * 128;

    float acc[4][4][4];
#pragma unroll
    for (int i = 0; i < 4; i++)
#pragma unroll
        for (int j = 0; j < 4; j++)
#pragma unroll
            for (int r = 0; r < 4; r++) acc[i][j][r] = 0.f;

    const int lr = tid >> 3;        // 0..31
    const int lc = (tid & 7) * 4;   // 0..28

    for (int k0 = 0; k0 < K; k0 += 32) {
#pragma unroll
        for (int i = 0; i < 4; i++) {
            int r = lr + i * 32;
            float4 v = *(const float4*)(A + (size_t)(bm + r) * K + k0 + lc);
            As[r][lc + 0] = f2tf32(v.x);
            As[r][lc + 1] = f2tf32(v.y);
            As[r][lc + 2] = f2tf32(v.z);
            As[r][lc + 3] = f2tf32(v.w);
        }
#pragma unroll
        for (int i = 0; i < 4; i++) {
            int r = lr + i * 32;
            float4 v = *(const float4*)(W + (size_t)(bn + r) * K + k0 + lc);
            Bs[r][lc + 0] = f2tf32(v.x);
            Bs[r][lc + 1] = f2tf32(v.y);
            Bs[r][lc + 2] = f2tf32(v.z);
            Bs[r][lc + 3] = f2tf32(v.w);
        }
        __syncthreads();

#pragma unroll
        for (int kk = 0; kk < 4; kk++) {
            uint32_t af[4][4];
            uint32_t bf[4][2];
#pragma unroll
            for (int mi = 0; mi < 4; mi++) {
                int rb = wm * 64 + mi * 16;
                af[mi][0] = As[rb + gid    ][kk * 8 + tig];
                af[mi][1] = As[rb + gid + 8][kk * 8 + tig];
                af[mi][2] = As[rb + gid    ][kk * 8 + tig + 4];
                af[mi][3] = As[rb + gid + 8][kk * 8 + tig + 4];
            }
#pragma unroll
            for (int ni = 0; ni < 4; ni++) {
                int nb = wn * 32 + ni * 8;
                bf[ni][0] = Bs[nb + gid][kk * 8 + tig];
                bf[ni][1] = Bs[nb + gid][kk * 8 + tig + 4];
            }
#pragma unroll
            for (int mi = 0; mi < 4; mi++)
#pragma unroll
                for (int ni = 0; ni < 4; ni++)
                    mma8(acc[mi][ni], af[mi], bf[ni]);
        }
        __syncthreads();
    }

    // Epilogue
#pragma unroll
    for (int mi = 0; mi < 4; mi++) {
#pragma unroll
        for (int ni = 0; ni < 4; ni++) {
            int r = bm + wm * 64 + mi * 16 + gid;
            int c = bn + wn * 32 + ni * 8 + 2 * tig;
            if (MODE == 0) {
                float b0 = bias[c], b1 = bias[c + 1];
                C[(size_t)r * N + c]           = acc[mi][ni][0] + b0;
                C[(size_t)r * N + c + 1]       = acc[mi][ni][1] + b1;
                C[(size_t)(r + 8) * N + c]     = acc[mi][ni][2] + b0;
                C[(size_t)(r + 8) * N + c + 1] = acc[mi][ni][3] + b1;
            } else {
                store_qkv(r,     c,     acc[mi][ni][0], bias);
                store_qkv(r,     c + 1, acc[mi][ni][1], bias);
                store_qkv(r + 8, c,     acc[mi][ni][2], bias);
                store_qkv(r + 8, c + 1, acc[mi][ni][3], bias);
            }
        }
    }
}

// ---------------------------------------------------------------------------
// Flash attention: one block = (head n, 64-query tile). 128 threads, 4 warps,
// each warp owns 16 query rows. Q frags register-resident; Q smem reused as P.
// ---------------------------------------------------------------------------
#define PADW 68  // 64 + 4: conflict-free fragment loads

__global__ void __launch_bounds__(128) attn_kernel()
{
    extern __shared__ uint32_t sh[];
    uint32_t* Qs = sh;                 // 64 x PADW (also P)
    uint32_t* Ks = sh + 64 * PADW;     // 64 x PADW
    uint32_t* Vs = sh + 2 * 64 * PADW; // 64 x PADW

    const int qt   = blockIdx.x;
    const int n    = blockIdx.y;
    const int tid  = threadIdx.x;
    const int warp = tid >> 5;
    const int lane = tid & 31;
    const int gid  = lane >> 2;
    const int tig  = lane & 3;
    const int rb   = warp * 16;

    const float* qptr  = g_q + ((size_t)n * SEQ + qt * 64) * HDIM;
    const float* kbase = g_k + (size_t)n * SEQ * HDIM;
    const float* vbase = g_v + (size_t)n * SEQ * HDIM;

    const int lr = tid >> 4;        // 0..7
    const int lc = (tid & 15) * 4;  // 0..60

    // Load Q tile (pre-scaled) -> smem as tf32
#pragma unroll
    for (int i = 0; i < 8; i++) {
        int r = lr + i * 8;
        float4 v = *(const float4*)(qptr + r * HDIM + lc);
        Qs[r * PADW + lc + 0] = f2tf32(v.x);
        Qs[r * PADW + lc + 1] = f2tf32(v.y);
        Qs[r * PADW + lc + 2] = f2tf32(v.z);
        Qs[r * PADW + lc + 3] = f2tf32(v.w);
    }
    __syncthreads();

    // Q fragments for this warp's 16 rows (whole D=64 -> 8 k-frags)
    uint32_t qa[8][4];
#pragma unroll
    for (int kf = 0; kf < 8; kf++) {
        qa[kf][0] = Qs[(rb + gid    ) * PADW + kf * 8 + tig];
        qa[kf][1] = Qs[(rb + gid + 8) * PADW + kf * 8 + tig];
        qa[kf][2] = Qs[(rb + gid    ) * PADW + kf * 8 + tig + 4];
        qa[kf][3] = Qs[(rb + gid + 8) * PADW + kf * 8 + tig + 4];
    }

    float mrow[2] = {-1e30f, -1e30f};
    float lrow[2] = {0.f, 0.f};
    float oacc[8][4];
#pragma unroll
    for (int j = 0; j < 8; j++)
#pragma unroll
        for (int r = 0; r < 4; r++) oacc[j][r] = 0.f;

    for (int kt = 0; kt < SEQ / 64; kt++) {
        __syncthreads();  // previous iteration done with Ks/Vs (and P reads)
#pragma unroll
        for (int i = 0; i < 8; i++) {
            int r = lr + i * 8;
            float4 kv = *(const float4*)(kbase + (size_t)(kt * 64 + r) * HDIM + lc);
            Ks[r * PADW + lc + 0] = f2tf32(kv.x);
            Ks[r * PADW + lc + 1] = f2tf32(kv.y);
            Ks[r * PADW + lc + 2] = f2tf32(kv.z);
            Ks[r * PADW + lc + 3] = f2tf32(kv.w);
            float4 vv = *(const float4*)(vbase + (size_t)(kt * 64 + r) * HDIM + lc);
            Vs[r * PADW + lc + 0] = f2tf32(vv.x);
            Vs[r * PADW + lc + 1] = f2tf32(vv.y);
            Vs[r * PADW + lc + 2] = f2tf32(vv.z);
            Vs[r * PADW + lc + 3] = f2tf32(vv.w);
        }
        __syncthreads();

        // S = Q @ K^T  (16 x 64 per warp)
        float sacc[8][4];
#pragma unroll
        for (int j = 0; j < 8; j++)
#pragma unroll
            for (int r = 0; r < 4; r++) sacc[j][r] = 0.f;

#pragma unroll
        for (int kf = 0; kf < 8; kf++) {
#pragma unroll
            for (int j = 0; j < 8; j++) {
                uint32_t bf[2];
                bf[0] = Ks[(j * 8 + gid) * PADW + kf * 8 + tig];
                bf[1] = Ks[(j * 8 + gid) * PADW + kf * 8 + tig + 4];
                mma8(sacc[j], qa[kf], bf);
            }
        }

        // Online softmax per row-half (row gid and gid+8)
#pragma unroll
        for (int hf = 0; hf < 2; hf++) {
            float tmax = -1e30f;
#pragma unroll
            for (int j = 0; j < 8; j++)
                tmax = fmaxf(tmax, fmaxf(sacc[j][2 * hf], sacc[j][2 * hf + 1]));
            tmax = fmaxf(tmax, __shfl_xor_sync(0xffffffffu, tmax, 1));
            tmax = fmaxf(tmax, __shfl_xor_sync(0xffffffffu, tmax, 2));

            float newm = fmaxf(mrow[hf], tmax);
            float corr = __expf(mrow[hf] - newm);
            mrow[hf] = newm;

            float rs = 0.f;
            int rloc = rb + gid + hf * 8;
#pragma unroll
            for (int j = 0; j < 8; j++) {
                float p0 = __expf(sacc[j][2 * hf]     - newm);
                float p1 = __expf(sacc[j][2 * hf + 1] - newm);
                rs += p0 + p1;
                Qs[rloc * PADW + j * 8 + 2 * tig]     = f2tf32(p0);
                Qs[rloc * PADW + j * 8 + 2 * tig + 1] = f2tf32(p1);
                oacc[j][2 * hf]     *= corr;
                oacc[j][2 * hf + 1] *= corr;
            }
            rs += __shfl_xor_sync(0xffffffffu, rs, 1);
            rs += __shfl_xor_sync(0xffffffffu, rs, 2);
            lrow[hf] = lrow[hf] * corr + rs;
        }
        __syncwarp();  // P visible to whole warp

        // O += P @ V
#pragma unroll
        for (int kf = 0; kf < 8; kf++) {
            uint32_t af[4];
            af[0] = Qs[(rb + gid    ) * PADW + kf * 8 + tig];
            af[1] = Qs[(rb + gid + 8) * PADW + kf * 8 + tig];
            af[2] = Qs[(rb + gid    ) * PADW + kf * 8 + tig + 4];
            af[3] = Qs[(rb + gid + 8) * PADW + kf * 8 + tig + 4];
#pragma unroll
            for (int j = 0; j < 8; j++) {
                uint32_t bf[2];
                bf[0] = Vs[(kf * 8 + tig    ) * PADW + j * 8 + gid];
                bf[1] = Vs[(kf * 8 + tig + 4) * PADW + j * 8 + gid];
                mma8(oacc[j], af, bf);
            }
        }
    }

    // Epilogue: normalize and write ctx in (s, b, e) layout
    const int b = n >> 4;   // HEADS = 16
    const int h = n & 15;
#pragma unroll
    for (int hf = 0; hf < 2; hf++) {
        float inv = 1.f / lrow[hf];
        int sg = qt * 64 + rb + gid + hf * 8;
        size_t rowoff = ((size_t)sg * BATCH + b) * EMB + h * HDIM;
#pragma unroll
        for (int j = 0; j < 8; j++) {
            g_ctx[rowoff + j * 8 + 2 * tig]     = oacc[j][2 * hf]     * inv;
            g_ctx[rowoff + j * 8 + 2 * tig + 1] = oacc[j][2 * hf + 1] * inv;
        }
    }
}

// ---------------------------------------------------------------------------
// kernel_launch
// ---------------------------------------------------------------------------
extern "C" void kernel_launch(void* const* d_in, const int* in_sizes, int n_in,
                              void* d_out, int out_size)
{
    (void)in_sizes; (void)n_in; (void)out_size;
    const float* query = (const float*)d_in[0];
    const float* w_in  = (const float*)d_in[1];
    const float* b_in  = (const float*)d_in[2];
    const float* w_out = (const float*)d_in[3];
    const float* b_out = (const float*)d_in[4];
    float* out = (float*)d_out;

    // 1) QKV projection: (8192 x 1024) @ (3072 x 1024)^T -> scattered q/k/v
    gemm_tf32<1><<<dim3(3072 / 128, 8192 / 128), 256>>>(
        query, w_in, b_in, nullptr, MROWS, 3 * EMB, EMB);

    // 2) Flash attention over 64 heads x 32 query tiles
    const int shbytes = 3 * 64 * PADW * 4;  // 52224 B dynamic smem
    cudaFuncSetAttribute(attn_kernel, cudaFuncAttributeMaxDynamicSharedMemorySize, shbytes);
    attn_kernel<<<dim3(SEQ / 64, NHEAD), 128, shbytes>>>();

    // 3) Out projection: ctx (8192 x 1024) @ (1024 x 1024)^T + bias -> out
    float* ctx_ptr = nullptr;
    cudaGetSymbolAddress((void**)&ctx_ptr, g_ctx);
    gemm_tf32<0><<<dim3(1024 / 128, 8192 / 128), 256>>>(
        ctx_ptr, w_out, b_out, out, MROWS, EMB, EMB);
}

// round 2
// speedup vs baseline: 1.5210x; 1.5210x over previous
#include <cuda_runtime.h>
#include <cstdint>

// Problem constants
#define SEQ   2048
#define BATCH 4
#define EMB   1024
#define HEADS 16
#define HDIM  64
#define NHEAD (BATCH*HEADS)     // 64
#define MROWS (SEQ*BATCH)       // 8192

// Scratch (device globals — no runtime allocation)
__device__ float g_q[(size_t)NHEAD * SEQ * HDIM];   // 32 MB, pre-scaled by D^-1/2
__device__ float g_k[(size_t)NHEAD * SEQ * HDIM];   // 32 MB
__device__ float g_v[(size_t)NHEAD * SEQ * HDIM];   // 32 MB
__device__ float g_ctx[(size_t)MROWS * EMB];        // 32 MB, (s,b,e) layout

// ---------------------------------------------------------------------------
// TF32 helpers
// ---------------------------------------------------------------------------
__device__ __forceinline__ uint32_t f2tf32(float x) {
    uint32_t y;
    asm("cvt.rna.tf32.f32 %0, %1;" : "=r"(y) : "f"(x));
    return y;
}

__device__ __forceinline__ void mma8(float* c, const uint32_t* a, const uint32_t* b) {
    asm volatile(
        "mma.sync.aligned.m16n8k8.row.col.f32.tf32.tf32.f32 "
        "{%0,%1,%2,%3}, {%4,%5,%6,%7}, {%8,%9}, {%0,%1,%2,%3};\n"
        : "+f"(c[0]), "+f"(c[1]), "+f"(c[2]), "+f"(c[3])
        : "r"(a[0]), "r"(a[1]), "r"(a[2]), "r"(a[3]), "r"(b[0]), "r"(b[1]));
}

// ---------------------------------------------------------------------------
// TF32 GEMM: C[M,N] = A[M,K] @ W[N,K]^T + bias
// Block 128x128, BK=32, 256 threads (8 warps, 2x4), warp tile 64x32.
// Smem row stride 36 (== 4 mod 32): fragment LDS pattern banks = 4*gid+tig,
// bijective over the warp -> conflict-free. (Old stride 33 gave 4-way.)
// MODE 0: plain store to C.
// MODE 1: qkv scatter into g_q (scaled), g_k, g_v.
// ---------------------------------------------------------------------------
#define GPAD 36

__device__ __forceinline__ void store_qkv(int m, int f, float v, const float* bias) {
    v += bias[f];
    int s = m >> 2;          // BATCH = 4
    int b = m & 3;
    int which = f >> 10;     // EMB = 1024
    int e = f & 1023;
    int h = e >> 6;          // HDIM = 64
    int d = e & 63;
    int idx = ((b * HEADS + h) * SEQ + s) * HDIM + d;
    if (which == 0)      g_q[idx] = v * 0.125f;   // 1/sqrt(64)
    else if (which == 1) g_k[idx] = v;
    else                 g_v[idx] = v;
}

template <int MODE>
__global__ void __launch_bounds__(256) gemm_tf32(
    const float* __restrict__ A, const float* __restrict__ W,
    const float* __restrict__ bias, float* __restrict__ C,
    int M, int N, int K)
{
    __shared__ uint32_t As[128][GPAD];
    __shared__ uint32_t Bs[128][GPAD];

    const int tid  = threadIdx.x;
    const int warp = tid >> 5;
    const int lane = tid & 31;
    const int gid  = lane >> 2;   // 0..7
    const int tig  = lane & 3;    // 0..3
    const int wm   = warp >> 2;   // 0..1
    const int wn   = warp & 3;    // 0..3

    const int bm = blockIdx.y * 128;
    const int bn = blockIdx.x * 128;

    float acc[4][4][4];
#pragma unroll
    for (int i = 0; i < 4; i++)
#pragma unroll
        for (int j = 0; j < 4; j++)
#pragma unroll
            for (int r = 0; r < 4; r++) acc[i][j][r] = 0.f;

    const int lr = tid >> 3;        // 0..31
    const int lc = (tid & 7) * 4;   // 0..28

    for (int k0 = 0; k0 < K; k0 += 32) {
#pragma unroll
        for (int i = 0; i < 4; i++) {
            int r = lr + i * 32;
            float4 v = *(const float4*)(A + (size_t)(bm + r) * K + k0 + lc);
            As[r][lc + 0] = f2tf32(v.x);
            As[r][lc + 1] = f2tf32(v.y);
            As[r][lc + 2] = f2tf32(v.z);
            As[r][lc + 3] = f2tf32(v.w);
        }
#pragma unroll
        for (int i = 0; i < 4; i++) {
            int r = lr + i * 32;
            float4 v = *(const float4*)(W + (size_t)(bn + r) * K + k0 + lc);
            Bs[r][lc + 0] = f2tf32(v.x);
            Bs[r][lc + 1] = f2tf32(v.y);
            Bs[r][lc + 2] = f2tf32(v.z);
            Bs[r][lc + 3] = f2tf32(v.w);
        }
        __syncthreads();

#pragma unroll
        for (int kk = 0; kk < 4; kk++) {
            uint32_t af[4][4];
            uint32_t bf[4][2];
#pragma unroll
            for (int mi = 0; mi < 4; mi++) {
                int rb = wm * 64 + mi * 16;
                af[mi][0] = As[rb + gid    ][kk * 8 + tig];
                af[mi][1] = As[rb + gid + 8][kk * 8 + tig];
                af[mi][2] = As[rb + gid    ][kk * 8 + tig + 4];
                af[mi][3] = As[rb + gid + 8][kk * 8 + tig + 4];
            }
#pragma unroll
            for (int ni = 0; ni < 4; ni++) {
                int nb = wn * 32 + ni * 8;
                bf[ni][0] = Bs[nb + gid][kk * 8 + tig];
                bf[ni][1] = Bs[nb + gid][kk * 8 + tig + 4];
            }
#pragma unroll
            for (int mi = 0; mi < 4; mi++)
#pragma unroll
                for (int ni = 0; ni < 4; ni++)
                    mma8(acc[mi][ni], af[mi], bf[ni]);
        }
        __syncthreads();
    }

    // Epilogue
#pragma unroll
    for (int mi = 0; mi < 4; mi++) {
#pragma unroll
        for (int ni = 0; ni < 4; ni++) {
            int r = bm + wm * 64 + mi * 16 + gid;
            int c = bn + wn * 32 + ni * 8 + 2 * tig;
            if (MODE == 0) {
                float b0 = bias[c], b1 = bias[c + 1];
                C[(size_t)r * N + c]           = acc[mi][ni][0] + b0;
                C[(size_t)r * N + c + 1]       = acc[mi][ni][1] + b1;
                C[(size_t)(r + 8) * N + c]     = acc[mi][ni][2] + b0;
                C[(size_t)(r + 8) * N + c + 1] = acc[mi][ni][3] + b1;
            } else {
                store_qkv(r,     c,     acc[mi][ni][0], bias);
                store_qkv(r,     c + 1, acc[mi][ni][1], bias);
                store_qkv(r + 8, c,     acc[mi][ni][2], bias);
                store_qkv(r + 8, c + 1, acc[mi][ni][3], bias);
            }
        }
    }
}

// ---------------------------------------------------------------------------
// Flash attention: one block = (head n, 64-query tile). 128 threads, 4 warps,
// each warp owns 16 query rows. Q frags register-resident; Q smem reused as P.
// Qs/Ks stride 68 (== 4 mod 32): S-loop frag loads conflict-free.
// Vs stride 72 (== 8 mod 32): PV B-frag loads (row varies by tig) conflict-free.
// ---------------------------------------------------------------------------
#define PADW 68
#define PADV 72

__global__ void __launch_bounds__(128) attn_kernel()
{
    extern __shared__ uint32_t sh[];
    uint32_t* Qs = sh;                 // 64 x PADW (also P)
    uint32_t* Ks = sh + 64 * PADW;     // 64 x PADW
    uint32_t* Vs = sh + 2 * 64 * PADW; // 64 x PADV

    const int qt   = blockIdx.x;
    const int n    = blockIdx.y;
    const int tid  = threadIdx.x;
    const int warp = tid >> 5;
    const int lane = tid & 31;
    const int gid  = lane >> 2;
    const int tig  = lane & 3;
    const int rb   = warp * 16;

    const float* qptr  = g_q + ((size_t)n * SEQ + qt * 64) * HDIM;
    const float* kbase = g_k + (size_t)n * SEQ * HDIM;
    const float* vbase = g_v + (size_t)n * SEQ * HDIM;

    const int lr = tid >> 4;        // 0..7
    const int lc = (tid & 15) * 4;  // 0..60

    // Load Q tile (pre-scaled) -> smem as tf32
#pragma unroll
    for (int i = 0; i < 8; i++) {
        int r = lr + i * 8;
        float4 v = *(const float4*)(qptr + r * HDIM + lc);
        Qs[r * PADW + lc + 0] = f2tf32(v.x);
        Qs[r * PADW + lc + 1] = f2tf32(v.y);
        Qs[r * PADW + lc + 2] = f2tf32(v.z);
        Qs[r * PADW + lc + 3] = f2tf32(v.w);
    }
    __syncthreads();

    // Q fragments for this warp's 16 rows (whole D=64 -> 8 k-frags)
    uint32_t qa[8][4];
#pragma unroll
    for (int kf = 0; kf < 8; kf++) {
        qa[kf][0] = Qs[(rb + gid    ) * PADW + kf * 8 + tig];
        qa[kf][1] = Qs[(rb + gid + 8) * PADW + kf * 8 + tig];
        qa[kf][2] = Qs[(rb + gid    ) * PADW + kf * 8 + tig + 4];
        qa[kf][3] = Qs[(rb + gid + 8) * PADW + kf * 8 + tig + 4];
    }

    float mrow[2] = {-1e30f, -1e30f};
    float lrow[2] = {0.f, 0.f};
    float oacc[8][4];
#pragma unroll
    for (int j = 0; j < 8; j++)
#pragma unroll
        for (int r = 0; r < 4; r++) oacc[j][r] = 0.f;

    for (int kt = 0; kt < SEQ / 64; kt++) {
        __syncthreads();  // previous iteration done with Ks/Vs (and P reads)
#pragma unroll
        for (int i = 0; i < 8; i++) {
            int r = lr + i * 8;
            float4 kv = *(const float4*)(kbase + (size_t)(kt * 64 + r) * HDIM + lc);
            Ks[r * PADW + lc + 0] = f2tf32(kv.x);
            Ks[r * PADW + lc + 1] = f2tf32(kv.y);
            Ks[r * PADW + lc + 2] = f2tf32(kv.z);
            Ks[r * PADW + lc + 3] = f2tf32(kv.w);
            float4 vv = *(const float4*)(vbase + (size_t)(kt * 64 + r) * HDIM + lc);
            Vs[r * PADV + lc + 0] = f2tf32(vv.x);
            Vs[r * PADV + lc + 1] = f2tf32(vv.y);
            Vs[r * PADV + lc + 2] = f2tf32(vv.z);
            Vs[r * PADV + lc + 3] = f2tf32(vv.w);
        }
        __syncthreads();

        // S = Q @ K^T  (16 x 64 per warp)
        float sacc[8][4];
#pragma unroll
        for (int j = 0; j < 8; j++)
#pragma unroll
            for (int r = 0; r < 4; r++) sacc[j][r] = 0.f;

#pragma unroll
        for (int kf = 0; kf < 8; kf++) {
#pragma unroll
            for (int j = 0; j < 8; j++) {
                uint32_t bf[2];
                bf[0] = Ks[(j * 8 + gid) * PADW + kf * 8 + tig];
                bf[1] = Ks[(j * 8 + gid) * PADW + kf * 8 + tig + 4];
                mma8(sacc[j], qa[kf], bf);
            }
        }

        // Online softmax per row-half (row gid and gid+8)
#pragma unroll
        for (int hf = 0; hf < 2; hf++) {
            float tmax = -1e30f;
#pragma unroll
            for (int j = 0; j < 8; j++)
                tmax = fmaxf(tmax, fmaxf(sacc[j][2 * hf], sacc[j][2 * hf + 1]));
            tmax = fmaxf(tmax, __shfl_xor_sync(0xffffffffu, tmax, 1));
            tmax = fmaxf(tmax, __shfl_xor_sync(0xffffffffu, tmax, 2));

            float newm = fmaxf(mrow[hf], tmax);
            float corr = __expf(mrow[hf] - newm);
            mrow[hf] = newm;

            float rs = 0.f;
            int rloc = rb + gid + hf * 8;
#pragma unroll
            for (int j = 0; j < 8; j++) {
                float p0 = __expf(sacc[j][2 * hf]     - newm);
                float p1 = __expf(sacc[j][2 * hf + 1] - newm);
                rs += p0 + p1;
                Qs[rloc * PADW + j * 8 + 2 * tig]     = f2tf32(p0);
                Qs[rloc * PADW + j * 8 + 2 * tig + 1] = f2tf32(p1);
                oacc[j][2 * hf]     *= corr;
                oacc[j][2 * hf + 1] *= corr;
            }
            rs += __shfl_xor_sync(0xffffffffu, rs, 1);
            rs += __shfl_xor_sync(0xffffffffu, rs, 2);
            lrow[hf] = lrow[hf] * corr + rs;
        }
        __syncwarp();  // P visible to whole warp

        // O += P @ V
#pragma unroll
        for (int kf = 0; kf < 8; kf++) {
            uint32_t af[4];
            af[0] = Qs[(rb + gid    ) * PADW + kf * 8 + tig];
            af[1] = Qs[(rb + gid + 8) * PADW + kf * 8 + tig];
            af[2] = Qs[(rb + gid    ) * PADW + kf * 8 + tig + 4];
            af[3] = Qs[(rb + gid + 8) * PADW + kf * 8 + tig + 4];
#pragma unroll
            for (int j = 0; j < 8; j++) {
                uint32_t bf[2];
                bf[0] = Vs[(kf * 8 + tig    ) * PADV + j * 8 + gid];
                bf[1] = Vs[(kf * 8 + tig + 4) * PADV + j * 8 + gid];
                mma8(oacc[j], af, bf);
            }
        }
    }

    // Epilogue: normalize and write ctx in (s, b, e) layout
    const int b = n >> 4;   // HEADS = 16
    const int h = n & 15;
#pragma unroll
    for (int hf = 0; hf < 2; hf++) {
        float inv = 1.f / lrow[hf];
        int sg = qt * 64 + rb + gid + hf * 8;
        size_t rowoff = ((size_t)sg * BATCH + b) * EMB + h * HDIM;
#pragma unroll
        for (int j = 0; j < 8; j++) {
            g_ctx[rowoff + j * 8 + 2 * tig]     = oacc[j][2 * hf]     * inv;
            g_ctx[rowoff + j * 8 + 2 * tig + 1] = oacc[j][2 * hf + 1] * inv;
        }
    }
}

// ---------------------------------------------------------------------------
// kernel_launch
// ---------------------------------------------------------------------------
extern "C" void kernel_launch(void* const* d_in, const int* in_sizes, int n_in,
                              void* d_out, int out_size)
{
    (void)in_sizes; (void)n_in; (void)out_size;
    const float* query = (const float*)d_in[0];
    const float* w_in  = (const float*)d_in[1];
    const float* b_in  = (const float*)d_in[2];
    const float* w_out = (const float*)d_in[3];
    const float* b_out = (const float*)d_in[4];
    float* out = (float*)d_out;

    // 1) QKV projection: (8192 x 1024) @ (3072 x 1024)^T -> scattered q/k/v
    gemm_tf32<1><<<dim3(3072 / 128, 8192 / 128), 256>>>(
        query, w_in, b_in, nullptr, MROWS, 3 * EMB, EMB);

    // 2) Flash attention over 64 heads x 32 query tiles
    const int shbytes = (2 * 64 * PADW + 64 * PADV) * 4;  // 53248 B dynamic smem
    cudaFuncSetAttribute(attn_kernel, cudaFuncAttributeMaxDynamicSharedMemorySize, shbytes);
    attn_kernel<<<dim3(SEQ / 64, NHEAD), 128, shbytes>>>();

    // 3) Out projection: ctx (8192 x 1024) @ (1024 x 1024)^T + bias -> out
    float* ctx_ptr = nullptr;
    cudaGetSymbolAddress((void**)&ctx_ptr, g_ctx);
    gemm_tf32<0><<<dim3(1024 / 128, 8192 / 128), 256>>>(
        ctx_ptr, w_out, b_out, out, MROWS, EMB, EMB);
}

// round 3
// speedup vs baseline: 1.6393x; 1.0778x over previous
#include <cuda_runtime.h>
#include <cstdint>

// Problem constants
#define SEQ   2048
#define BATCH 4
#define EMB   1024
#define HEADS 16
#define HDIM  64
#define NHEAD (BATCH*HEADS)     // 64
#define MROWS (SEQ*BATCH)       // 8192

// Scratch (device globals — no runtime allocation)
__device__ float g_q[(size_t)NHEAD * SEQ * HDIM];   // tf32-rounded, q pre-scaled
__device__ float g_k[(size_t)NHEAD * SEQ * HDIM];
__device__ float g_v[(size_t)NHEAD * SEQ * HDIM];
__device__ float g_ctx[(size_t)MROWS * EMB];        // tf32-rounded, (s,b,e)
__device__ float g_qt[(size_t)MROWS * EMB];         // query, tf32-rounded
__device__ float g_wi[(size_t)3 * EMB * EMB];       // in_proj_weight, tf32-rounded
__device__ float g_wo[(size_t)EMB * EMB];           // out_proj_weight, tf32-rounded

// ---------------------------------------------------------------------------
// TF32 helpers
// ---------------------------------------------------------------------------
__device__ __forceinline__ uint32_t f2tf32(float x) {
    uint32_t y;
    asm("cvt.rna.tf32.f32 %0, %1;" : "=r"(y) : "f"(x));
    return y;
}

__device__ __forceinline__ void mma8(float* c, const uint32_t* a, const uint32_t* b) {
    asm volatile(
        "mma.sync.aligned.m16n8k8.row.col.f32.tf32.tf32.f32 "
        "{%0,%1,%2,%3}, {%4,%5,%6,%7}, {%8,%9}, {%0,%1,%2,%3};\n"
        : "+f"(c[0]), "+f"(c[1]), "+f"(c[2]), "+f"(c[3])
        : "r"(a[0]), "r"(a[1]), "r"(a[2]), "r"(a[3]), "r"(b[0]), "r"(b[1]));
}

__device__ __forceinline__ uint32_t smem_u32(const void* p) {
    uint32_t a;
    asm("{ .reg .u64 t; cvta.to.shared.u64 t, %1; cvt.u32.u64 %0, t; }" : "=r"(a) : "l"(p));
    return a;
}

__device__ __forceinline__ void cp16(uint32_t dst, const void* src) {
    asm volatile("cp.async.cg.shared.global [%0], [%1], 16;" :: "r"(dst), "l"(src));
}

// ---------------------------------------------------------------------------
// Elementwise fp32 -> tf32-rounded (bits stored as float)
// ---------------------------------------------------------------------------
__global__ void __launch_bounds__(256) conv_tf32(const float* __restrict__ src,
                                                 float* __restrict__ dst, int n4)
{
    int i = blockIdx.x * blockDim.x + threadIdx.x;
    if (i < n4) {
        float4 v = ((const float4*)src)[i];
        uint4 o;
        o.x = f2tf32(v.x); o.y = f2tf32(v.y); o.z = f2tf32(v.z); o.w = f2tf32(v.w);
        ((uint4*)dst)[i] = o;
    }
}

// ---------------------------------------------------------------------------
// TF32 GEMM, cp.async double-buffered: C[M,N] = A[M,K] @ W[N,K]^T + bias
// A and W are PRE-CONVERTED tf32 bits. Block 128x128, BK=32, 256 threads
// (8 warps 2x4, warp tile 64x32). Smem stride 36 (==4 mod 32): frag loads
// conflict-free. MODE 0: plain store. MODE 1: qkv scatter (tf32-rounded).
// ---------------------------------------------------------------------------
#define GPAD 36
#define STAGE_WORDS (2 * 128 * GPAD)   // A + B for one stage

__device__ __forceinline__ void store_qkv(int m, int f, float v, const float* bias) {
    v += bias[f];
    int s = m >> 2;          // BATCH = 4
    int b = m & 3;
    int which = f >> 10;     // EMB = 1024
    int e = f & 1023;
    int h = e >> 6;          // HDIM = 64
    int d = e & 63;
    int idx = ((b * HEADS + h) * SEQ + s) * HDIM + d;
    if (which == 0)      g_q[idx] = __uint_as_float(f2tf32(v * 0.125f));
    else if (which == 1) g_k[idx] = __uint_as_float(f2tf32(v));
    else                 g_v[idx] = __uint_as_float(f2tf32(v));
}

template <int MODE>
__global__ void __launch_bounds__(256) gemm_tf32(
    const float* __restrict__ A, const float* __restrict__ W,
    const float* __restrict__ bias, float* __restrict__ C,
    int M, int N, int K)
{
    extern __shared__ uint32_t sh[];

    const int tid  = threadIdx.x;
    const int warp = tid >> 5;
    const int lane = tid & 31;
    const int gid  = lane >> 2;   // 0..7
    const int tig  = lane & 3;    // 0..3
    const int wm   = warp >> 2;   // 0..1
    const int wn   = warp & 3;    // 0..3

    const int bm = blockIdx.y * 128;
    const int bn = blockIdx.x * 128;

    const int lr = tid >> 3;        // 0..31
    const int lc = (tid & 7) * 4;   // 0..28

    // Per-thread smem dst offsets (bytes) for the two stages
    uint32_t base = smem_u32(sh);
    uint32_t a_dst[2], b_dst[2];
#pragma unroll
    for (int st = 0; st < 2; st++) {
        a_dst[st] = base + (st * STAGE_WORDS + lr * GPAD + lc) * 4;
        b_dst[st] = base + (st * STAGE_WORDS + 128 * GPAD + lr * GPAD + lc) * 4;
    }
    const float* a_src = A + (size_t)(bm + lr) * K + lc;
    const float* w_src = W + (size_t)(bn + lr) * K + lc;

    const int nT = K / 32;

    // issue stage t into buffer t&1
    auto issue = [&](int t) {
        int st = t & 1;
        int k0 = t * 32;
#pragma unroll
        for (int i = 0; i < 4; i++)
            cp16(a_dst[st] + i * 32 * GPAD * 4, a_src + (size_t)i * 32 * K + k0);
#pragma unroll
        for (int i = 0; i < 4; i++)
            cp16(b_dst[st] + i * 32 * GPAD * 4, w_src + (size_t)i * 32 * K + k0);
        asm volatile("cp.async.commit_group;");
    };

    float acc[4][4][4];
#pragma unroll
    for (int i = 0; i < 4; i++)
#pragma unroll
        for (int j = 0; j < 4; j++)
#pragma unroll
            for (int r = 0; r < 4; r++) acc[i][j][r] = 0.f;

    issue(0);

    for (int t = 0; t < nT; t++) {
        if (t + 1 < nT) {
            issue(t + 1);
            asm volatile("cp.async.wait_group 1;");
        } else {
            asm volatile("cp.async.wait_group 0;");
        }
        __syncthreads();

        const uint32_t* As = sh + (t & 1) * STAGE_WORDS;
        const uint32_t* Bs = As + 128 * GPAD;

#pragma unroll
        for (int kk = 0; kk < 4; kk++) {
            uint32_t af[4][4];
            uint32_t bf[4][2];
#pragma unroll
            for (int mi = 0; mi < 4; mi++) {
                int rb = wm * 64 + mi * 16;
                af[mi][0] = As[(rb + gid    ) * GPAD + kk * 8 + tig];
                af[mi][1] = As[(rb + gid + 8) * GPAD + kk * 8 + tig];
                af[mi][2] = As[(rb + gid    ) * GPAD + kk * 8 + tig + 4];
                af[mi][3] = As[(rb + gid + 8) * GPAD + kk * 8 + tig + 4];
            }
#pragma unroll
            for (int ni = 0; ni < 4; ni++) {
                int nb = wn * 32 + ni * 8;
                bf[ni][0] = Bs[(nb + gid) * GPAD + kk * 8 + tig];
                bf[ni][1] = Bs[(nb + gid) * GPAD + kk * 8 + tig + 4];
            }
#pragma unroll
            for (int mi = 0; mi < 4; mi++)
#pragma unroll
                for (int ni = 0; ni < 4; ni++)
                    mma8(acc[mi][ni], af[mi], bf[ni]);
        }
        __syncthreads();  // buffer t&1 free for stage t+2
    }

    // Epilogue
#pragma unroll
    for (int mi = 0; mi < 4; mi++) {
#pragma unroll
        for (int ni = 0; ni < 4; ni++) {
            int r = bm + wm * 64 + mi * 16 + gid;
            int c = bn + wn * 32 + ni * 8 + 2 * tig;
            if (MODE == 0) {
                float b0 = bias[c], b1 = bias[c + 1];
                C[(size_t)r * N + c]           = acc[mi][ni][0] + b0;
                C[(size_t)r * N + c + 1]       = acc[mi][ni][1] + b1;
                C[(size_t)(r + 8) * N + c]     = acc[mi][ni][2] + b0;
                C[(size_t)(r + 8) * N + c + 1] = acc[mi][ni][3] + b1;
            } else {
                store_qkv(r,     c,     acc[mi][ni][0], bias);
                store_qkv(r,     c + 1, acc[mi][ni][1], bias);
                store_qkv(r + 8, c,     acc[mi][ni][2], bias);
                store_qkv(r + 8, c + 1, acc[mi][ni][3], bias);
            }
        }
    }
}

// ---------------------------------------------------------------------------
// Flash attention: one block = (head n, 128-query tile), 256 threads, 8 warps,
// each warp owns 16 query rows; K/V tiles (64 keys) shared by all 8 warps.
// Inputs are already tf32-rounded -> raw bit copies into smem.
// Qs/Ks stride 68 (==4 mod 32), Vs stride 72 (==8 mod 32): conflict-free.
// ---------------------------------------------------------------------------
#define QROWS 128
#define PADW 68
#define PADV 72

__global__ void __launch_bounds__(256) attn_kernel()
{
    extern __shared__ uint32_t sh[];
    uint32_t* Qs = sh;                    // QROWS x PADW (also P)
    uint32_t* Ks = sh + QROWS * PADW;     // 64 x PADW
    uint32_t* Vs = Ks + 64 * PADW;        // 64 x PADV

    const int qt   = blockIdx.x;
    const int n    = blockIdx.y;
    const int tid  = threadIdx.x;
    const int warp = tid >> 5;
    const int lane = tid & 31;
    const int gid  = lane >> 2;
    const int tig  = lane & 3;
    const int rb   = warp * 16;

    const float* qptr  = g_q + ((size_t)n * SEQ + qt * QROWS) * HDIM;
    const float* kbase = g_k + (size_t)n * SEQ * HDIM;
    const float* vbase = g_v + (size_t)n * SEQ * HDIM;

    const int lr = tid >> 4;        // 0..15
    const int lc = (tid & 15) * 4;  // 0..60

    // Load Q tile (128 rows) -> smem, raw bits
#pragma unroll
    for (int i = 0; i < 8; i++) {
        int r = lr + i * 16;
        uint4 v = *(const uint4*)(qptr + (size_t)r * HDIM + lc);
        *(uint4*)&Qs[r * PADW + lc] = v;
    }
    __syncthreads();

    // Q fragments for this warp's 16 rows (D=64 -> 8 k-frags)
    uint32_t qa[8][4];
#pragma unroll
    for (int kf = 0; kf < 8; kf++) {
        qa[kf][0] = Qs[(rb + gid    ) * PADW + kf * 8 + tig];
        qa[kf][1] = Qs[(rb + gid + 8) * PADW + kf * 8 + tig];
        qa[kf][2] = Qs[(rb + gid    ) * PADW + kf * 8 + tig + 4];
        qa[kf][3] = Qs[(rb + gid + 8) * PADW + kf * 8 + tig + 4];
    }

    float mrow[2] = {-1e30f, -1e30f};
    float lrow[2] = {0.f, 0.f};
    float oacc[8][4];
#pragma unroll
    for (int j = 0; j < 8; j++)
#pragma unroll
        for (int r = 0; r < 4; r++) oacc[j][r] = 0.f;

    for (int kt = 0; kt < SEQ / 64; kt++) {
        __syncthreads();  // previous iteration done with Ks/Vs (and P reads)
#pragma unroll
        for (int i = 0; i < 4; i++) {
            int r = lr + i * 16;
            uint4 kv = *(const uint4*)(kbase + (size_t)(kt * 64 + r) * HDIM + lc);
            *(uint4*)&Ks[r * PADW + lc] = kv;
            uint4 vv = *(const uint4*)(vbase + (size_t)(kt * 64 + r) * HDIM + lc);
            *(uint4*)&Vs[r * PADV + lc] = vv;
        }
        __syncthreads();

        // S = Q @ K^T  (16 x 64 per warp)
        float sacc[8][4];
#pragma unroll
        for (int j = 0; j < 8; j++)
#pragma unroll
            for (int r = 0; r < 4; r++) sacc[j][r] = 0.f;

#pragma unroll
        for (int kf = 0; kf < 8; kf++) {
#pragma unroll
            for (int j = 0; j < 8; j++) {
                uint32_t bf[2];
                bf[0] = Ks[(j * 8 + gid) * PADW + kf * 8 + tig];
                bf[1] = Ks[(j * 8 + gid) * PADW + kf * 8 + tig + 4];
                mma8(sacc[j], qa[kf], bf);
            }
        }

        // Online softmax per row-half (row gid and gid+8)
#pragma unroll
        for (int hf = 0; hf < 2; hf++) {
            float tmax = -1e30f;
#pragma unroll
            for (int j = 0; j < 8; j++)
                tmax = fmaxf(tmax, fmaxf(sacc[j][2 * hf], sacc[j][2 * hf + 1]));
            tmax = fmaxf(tmax, __shfl_xor_sync(0xffffffffu, tmax, 1));
            tmax = fmaxf(tmax, __shfl_xor_sync(0xffffffffu, tmax, 2));

            float newm = fmaxf(mrow[hf], tmax);
            float corr = __expf(mrow[hf] - newm);
            mrow[hf] = newm;

            float rs = 0.f;
            int rloc = rb + gid + hf * 8;
#pragma unroll
            for (int j = 0; j < 8; j++) {
                float p0 = __expf(sacc[j][2 * hf]     - newm);
                float p1 = __expf(sacc[j][2 * hf + 1] - newm);
                rs += p0 + p1;
                Qs[rloc * PADW + j * 8 + 2 * tig]     = f2tf32(p0);
                Qs[rloc * PADW + j * 8 + 2 * tig + 1] = f2tf32(p1);
                oacc[j][2 * hf]     *= corr;
                oacc[j][2 * hf + 1] *= corr;
            }
            rs += __shfl_xor_sync(0xffffffffu, rs, 1);
            rs += __shfl_xor_sync(0xffffffffu, rs, 2);
            lrow[hf] = lrow[hf] * corr + rs;
        }
        __syncwarp();  // P visible to whole warp

        // O += P @ V
#pragma unroll
        for (int kf = 0; kf < 8; kf++) {
            uint32_t af[4];
            af[0] = Qs[(rb + gid    ) * PADW + kf * 8 + tig];
            af[1] = Qs[(rb + gid + 8) * PADW + kf * 8 + tig];
            af[2] = Qs[(rb + gid    ) * PADW + kf * 8 + tig + 4];
            af[3] = Qs[(rb + gid + 8) * PADW + kf * 8 + tig + 4];
#pragma unroll
            for (int j = 0; j < 8; j++) {
                uint32_t bf[2];
                bf[0] = Vs[(kf * 8 + tig    ) * PADV + j * 8 + gid];
                bf[1] = Vs[(kf * 8 + tig + 4) * PADV + j * 8 + gid];
                mma8(oacc[j], af, bf);
            }
        }
    }

    // Epilogue: normalize and write ctx (tf32-rounded) in (s, b, e) layout
    const int b = n >> 4;   // HEADS = 16
    const int h = n & 15;
#pragma unroll
    for (int hf = 0; hf < 2; hf++) {
        float inv = 1.f / lrow[hf];
        int sg = qt * QROWS + rb + gid + hf * 8;
        size_t rowoff = ((size_t)sg * BATCH + b) * EMB + h * HDIM;
#pragma unroll
        for (int j = 0; j < 8; j++) {
            g_ctx[rowoff + j * 8 + 2 * tig]     =
                __uint_as_float(f2tf32(oacc[j][2 * hf]     * inv));
            g_ctx[rowoff + j * 8 + 2 * tig + 1] =
                __uint_as_float(f2tf32(oacc[j][2 * hf + 1] * inv));
        }
    }
}

// ---------------------------------------------------------------------------
// kernel_launch
// ---------------------------------------------------------------------------
extern "C" void kernel_launch(void* const* d_in, const int* in_sizes, int n_in,
                              void* d_out, int out_size)
{
    (void)in_sizes; (void)n_in; (void)out_size;
    const float* query = (const float*)d_in[0];
    const float* w_in  = (const float*)d_in[1];
    const float* b_in  = (const float*)d_in[2];
    const float* w_out = (const float*)d_in[3];
    const float* b_out = (const float*)d_in[4];
    float* out = (float*)d_out;

    float *qt_p, *wi_p, *wo_p, *ctx_p;
    cudaGetSymbolAddress((void**)&qt_p,  g_qt);
    cudaGetSymbolAddress((void**)&wi_p,  g_wi);
    cudaGetSymbolAddress((void**)&wo_p,  g_wo);
    cudaGetSymbolAddress((void**)&ctx_p, g_ctx);

    // 0) One-time tf32 conversions (pure bandwidth, ~50MB)
    conv_tf32<<<(MROWS * EMB / 4 + 255) / 256, 256>>>(query, qt_p, MROWS * EMB / 4);
    conv_tf32<<<(3 * EMB * EMB / 4 + 255) / 256, 256>>>(w_in, wi_p, 3 * EMB * EMB / 4);
    conv_tf32<<<(EMB * EMB / 4 + 255) / 256, 256>>>(w_out, wo_p, EMB * EMB / 4);

    const int gemm_sh = 2 * STAGE_WORDS * 4;  // 73728 B
    cudaFuncSetAttribute(gemm_tf32<1>, cudaFuncAttributeMaxDynamicSharedMemorySize, gemm_sh);
    cudaFuncSetAttribute(gemm_tf32<0>, cudaFuncAttributeMaxDynamicSharedMemorySize, gemm_sh);

    // 1) QKV projection: (8192 x 1024) @ (3072 x 1024)^T -> scattered q/k/v
    gemm_tf32<1><<<dim3(3072 / 128, 8192 / 128), 256, gemm_sh>>>(
        qt_p, wi_p, b_in, nullptr, MROWS, 3 * EMB, EMB);

    // 2) Flash attention: 64 heads x 16 query tiles of 128
    const int attn_sh = (QROWS * PADW + 64 * PADW + 64 * PADV) * 4;  // 70656 B
    cudaFuncSetAttribute(attn_kernel, cudaFuncAttributeMaxDynamicSharedMemorySize, attn_sh);
    attn_kernel<<<dim3(SEQ / QROWS, NHEAD), 256, attn_sh>>>();

    // 3) Out projection: ctx (8192 x 1024) @ (1024 x 1024)^T + bias -> out
    gemm_tf32<0><<<dim3(1024 / 128, 8192 / 128), 256, gemm_sh>>>(
        ctx_p, wo_p, b_out, out, MROWS, EMB, EMB);
}

// round 4
// speedup vs baseline: 1.7259x; 1.0528x over previous
#include <cuda_runtime.h>
#include <cstdint>

// Problem constants
#define SEQ   2048
#define BATCH 4
#define EMB   1024
#define HEADS 16
#define HDIM  64
#define NHEAD (BATCH*HEADS)     // 64
#define MROWS (SEQ*BATCH)       // 8192

// Scratch (device globals — no runtime allocation)
__device__ float g_q[(size_t)NHEAD * SEQ * HDIM];   // tf32-rounded, q pre-scaled
__device__ float g_k[(size_t)NHEAD * SEQ * HDIM];
__device__ float g_v[(size_t)NHEAD * SEQ * HDIM];
__device__ float g_ctx[(size_t)MROWS * EMB];        // tf32-rounded, (s,b,e)
__device__ float g_qt[(size_t)MROWS * EMB];         // query, tf32-rounded
__device__ float g_wi[(size_t)3 * EMB * EMB];       // in_proj_weight, tf32-rounded
__device__ float g_wo[(size_t)EMB * EMB];           // out_proj_weight, tf32-rounded

// ---------------------------------------------------------------------------
// Helpers
// ---------------------------------------------------------------------------
__device__ __forceinline__ uint32_t f2tf32(float x) {
    uint32_t y;
    asm("cvt.rna.tf32.f32 %0, %1;" : "=r"(y) : "f"(x));
    return y;
}

__device__ __forceinline__ void mma8(float* c, const uint32_t* a, const uint32_t* b) {
    asm volatile(
        "mma.sync.aligned.m16n8k8.row.col.f32.tf32.tf32.f32 "
        "{%0,%1,%2,%3}, {%4,%5,%6,%7}, {%8,%9}, {%0,%1,%2,%3};\n"
        : "+f"(c[0]), "+f"(c[1]), "+f"(c[2]), "+f"(c[3])
        : "r"(a[0]), "r"(a[1]), "r"(a[2]), "r"(a[3]), "r"(b[0]), "r"(b[1]));
}

__device__ __forceinline__ uint32_t smem_u32(const void* p) {
    uint32_t a;
    asm("{ .reg .u64 t; cvta.to.shared.u64 t, %1; cvt.u32.u64 %0, t; }" : "=r"(a) : "l"(p));
    return a;
}

__device__ __forceinline__ void cp16(uint32_t dst, const void* src) {
    asm volatile("cp.async.cg.shared.global [%0], [%1], 16;" :: "r"(dst), "l"(src));
}
__device__ __forceinline__ void cp_commit() {
    asm volatile("cp.async.commit_group;");
}

// ---------------------------------------------------------------------------
// Elementwise fp32 -> tf32-rounded (bits stored as float)
// ---------------------------------------------------------------------------
__global__ void __launch_bounds__(256) conv_tf32(const float* __restrict__ src,
                                                 float* __restrict__ dst, int n4)
{
    int i = blockIdx.x * blockDim.x + threadIdx.x;
    if (i < n4) {
        float4 v = ((const float4*)src)[i];
        uint4 o;
        o.x = f2tf32(v.x); o.y = f2tf32(v.y); o.z = f2tf32(v.z); o.w = f2tf32(v.w);
        ((uint4*)dst)[i] = o;
    }
}

// ---------------------------------------------------------------------------
// TF32 GEMM, 3-stage cp.async pipeline, 1 sync/iter, frag software pipeline.
// C[M,N] = A[M,K] @ W[N,K]^T + bias.  A, W pre-converted tf32 bits.
// Block 128x128, BK=32, 256 threads (8 warps 2x4, warp tile 64x32).
// Smem stride 36 (==4 mod 32): fragment loads conflict-free.
// ---------------------------------------------------------------------------
#define GPAD 36
#define STAGE_WORDS (2 * 128 * GPAD)   // A + B for one stage
#define NSTAGE 3

__device__ __forceinline__ void store_qkv(int m, int f, float v, const float* bias) {
    v += bias[f];
    int s = m >> 2;          // BATCH = 4
    int b = m & 3;
    int which = f >> 10;     // EMB = 1024
    int e = f & 1023;
    int h = e >> 6;          // HDIM = 64
    int d = e & 63;
    int idx = ((b * HEADS + h) * SEQ + s) * HDIM + d;
    if (which == 0)      g_q[idx] = __uint_as_float(f2tf32(v * 0.125f));
    else if (which == 1) g_k[idx] = __uint_as_float(f2tf32(v));
    else                 g_v[idx] = __uint_as_float(f2tf32(v));
}

template <int MODE>
__global__ void __launch_bounds__(256, 2) gemm_tf32(
    const float* __restrict__ A, const float* __restrict__ W,
    const float* __restrict__ bias, float* __restrict__ C,
    int M, int N, int K)
{
    extern __shared__ uint32_t sh[];

    const int tid  = threadIdx.x;
    const int warp = tid >> 5;
    const int lane = tid & 31;
    const int gid  = lane >> 2;   // 0..7
    const int tig  = lane & 3;    // 0..3
    const int wm   = warp >> 2;   // 0..1
    const int wn   = warp & 3;    // 0..3

    const int bm = blockIdx.y * 128;
    const int bn = blockIdx.x * 128;

    const int lr = tid >> 3;        // 0..31
    const int lc = (tid & 7) * 4;   // 0..28

    uint32_t base = smem_u32(sh);
    uint32_t a_dst0 = base + (lr * GPAD + lc) * 4;
    uint32_t b_dst0 = base + (128 * GPAD + lr * GPAD + lc) * 4;

    const float* a_src = A + (size_t)(bm + lr) * K + lc;
    const float* w_src = W + (size_t)(bn + lr) * K + lc;

    const int nT = K / 32;

    auto issue = [&](int t) {
        int st = t % NSTAGE;
        int k0 = t * 32;
        uint32_t soff = (uint32_t)st * STAGE_WORDS * 4;
#pragma unroll
        for (int i = 0; i < 4; i++)
            cp16(a_dst0 + soff + i * 32 * GPAD * 4, a_src + (size_t)i * 32 * K + k0);
#pragma unroll
        for (int i = 0; i < 4; i++)
            cp16(b_dst0 + soff + i * 32 * GPAD * 4, w_src + (size_t)i * 32 * K + k0);
        cp_commit();
    };

    float acc[4][4][4];
#pragma unroll
    for (int i = 0; i < 4; i++)
#pragma unroll
        for (int j = 0; j < 4; j++)
#pragma unroll
            for (int r = 0; r < 4; r++) acc[i][j][r] = 0.f;

    issue(0);
    issue(1);

    for (int t = 0; t < nT; t++) {
        if (t < nT - 1) asm volatile("cp.async.wait_group 1;");
        else            asm volatile("cp.async.wait_group 0;");
        __syncthreads();          // stage t visible everywhere; buf (t+2)%3 free
        if (t + 2 < nT) issue(t + 2);

        const uint32_t* As = sh + (t % NSTAGE) * STAGE_WORDS;
        const uint32_t* Bs = As + 128 * GPAD;

        auto loadfrag = [&](int kk, uint32_t af[4][4], uint32_t bf[4][2]) {
#pragma unroll
            for (int mi = 0; mi < 4; mi++) {
                int rb = wm * 64 + mi * 16;
                af[mi][0] = As[(rb + gid    ) * GPAD + kk * 8 + tig];
                af[mi][1] = As[(rb + gid + 8) * GPAD + kk * 8 + tig];
                af[mi][2] = As[(rb + gid    ) * GPAD + kk * 8 + tig + 4];
                af[mi][3] = As[(rb + gid + 8) * GPAD + kk * 8 + tig + 4];
            }
#pragma unroll
            for (int ni = 0; ni < 4; ni++) {
                int nb = wn * 32 + ni * 8;
                bf[ni][0] = Bs[(nb + gid) * GPAD + kk * 8 + tig];
                bf[ni][1] = Bs[(nb + gid) * GPAD + kk * 8 + tig + 4];
            }
        };

        uint32_t af[2][4][4], bf[2][4][2];
        loadfrag(0, af[0], bf[0]);
#pragma unroll
        for (int kk = 0; kk < 4; kk++) {
            if (kk < 3) loadfrag(kk + 1, af[(kk + 1) & 1], bf[(kk + 1) & 1]);
            uint32_t (*a)[4] = af[kk & 1];
            uint32_t (*b)[2] = bf[kk & 1];
#pragma unroll
            for (int mi = 0; mi < 4; mi++)
#pragma unroll
                for (int ni = 0; ni < 4; ni++)
                    mma8(acc[mi][ni], a[mi], b[ni]);
        }
        // no trailing sync: next iter's barrier protects buffer reuse
    }

    // Epilogue
#pragma unroll
    for (int mi = 0; mi < 4; mi++) {
#pragma unroll
        for (int ni = 0; ni < 4; ni++) {
            int r = bm + wm * 64 + mi * 16 + gid;
            int c = bn + wn * 32 + ni * 8 + 2 * tig;
            if (MODE == 0) {
                float b0 = bias[c], b1 = bias[c + 1];
                C[(size_t)r * N + c]           = acc[mi][ni][0] + b0;
                C[(size_t)r * N + c + 1]       = acc[mi][ni][1] + b1;
                C[(size_t)(r + 8) * N + c]     = acc[mi][ni][2] + b0;
                C[(size_t)(r + 8) * N + c + 1] = acc[mi][ni][3] + b1;
            } else {
                store_qkv(r,     c,     acc[mi][ni][0], bias);
                store_qkv(r,     c + 1, acc[mi][ni][1], bias);
                store_qkv(r + 8, c,     acc[mi][ni][2], bias);
                store_qkv(r + 8, c + 1, acc[mi][ni][3], bias);
            }
        }
    }
}

// ---------------------------------------------------------------------------
// Flash attention: one block = (head n, 128-query tile), 256 threads, 8 warps.
// K/V tiles double-buffered via cp.async (load kt+1 under compute kt).
// Qs/Ks stride 68 (==4 mod 32), Vs stride 72 (==8 mod 32): conflict-free.
// ---------------------------------------------------------------------------
#define QROWS 128
#define PADW 68
#define PADV 72
#define KSTG_WORDS (64 * PADW)
#define VSTG_WORDS (64 * PADV)

__global__ void __launch_bounds__(256, 2) attn_kernel()
{
    extern __shared__ uint32_t sh[];
    uint32_t* Qs  = sh;                          // QROWS x PADW (also P)
    uint32_t* Ks0 = sh + QROWS * PADW;           // 2 stages x 64 x PADW
    uint32_t* Vs0 = Ks0 + 2 * KSTG_WORDS;        // 2 stages x 64 x PADV

    const int qt   = blockIdx.x;
    const int n    = blockIdx.y;
    const int tid  = threadIdx.x;
    const int warp = tid >> 5;
    const int lane = tid & 31;
    const int gid  = lane >> 2;
    const int tig  = lane & 3;
    const int rb   = warp * 16;

    const float* qptr  = g_q + ((size_t)n * SEQ + qt * QROWS) * HDIM;
    const float* kbase = g_k + (size_t)n * SEQ * HDIM;
    const float* vbase = g_v + (size_t)n * SEQ * HDIM;

    const int lr = tid >> 4;        // 0..15
    const int lc = (tid & 15) * 4;  // 0..60

    uint32_t base   = smem_u32(sh);
    uint32_t k_dst0 = base + (QROWS * PADW + lr * PADW + lc) * 4;
    uint32_t v_dst0 = base + (QROWS * PADW + 2 * KSTG_WORDS + lr * PADV + lc) * 4;

    auto issueKV = [&](int kt) {
        int st = kt & 1;
#pragma unroll
        for (int i = 0; i < 4; i++) {
            int r = lr + i * 16;
            cp16(k_dst0 + (st * KSTG_WORDS + i * 16 * PADW) * 4,
                 kbase + (size_t)(kt * 64 + r) * HDIM + lc);
            cp16(v_dst0 + (st * VSTG_WORDS + i * 16 * PADV) * 4,
                 vbase + (size_t)(kt * 64 + r) * HDIM + lc);
        }
        cp_commit();
    };

    issueKV(0);

    // Load Q tile (128 rows) -> smem, raw bits (already tf32-rounded)
#pragma unroll
    for (int i = 0; i < 8; i++) {
        int r = lr + i * 16;
        uint4 v = *(const uint4*)(qptr + (size_t)r * HDIM + lc);
        *(uint4*)&Qs[r * PADW + lc] = v;
    }
    __syncthreads();

    // Q fragments for this warp's 16 rows (D=64 -> 8 k-frags)
    uint32_t qa[8][4];
#pragma unroll
    for (int kf = 0; kf < 8; kf++) {
        qa[kf][0] = Qs[(rb + gid    ) * PADW + kf * 8 + tig];
        qa[kf][1] = Qs[(rb + gid + 8) * PADW + kf * 8 + tig];
        qa[kf][2] = Qs[(rb + gid    ) * PADW + kf * 8 + tig + 4];
        qa[kf][3] = Qs[(rb + gid + 8) * PADW + kf * 8 + tig + 4];
    }

    float mrow[2] = {-1e30f, -1e30f};
    float lrow[2] = {0.f, 0.f};
    float oacc[8][4];
#pragma unroll
    for (int j = 0; j < 8; j++)
#pragma unroll
        for (int r = 0; r < 4; r++) oacc[j][r] = 0.f;

    const int nT = SEQ / 64;
    for (int kt = 0; kt < nT; kt++) {
        asm volatile("cp.async.wait_group 0;");
        __syncthreads();   // stage kt visible; prev compute done -> alt buf free
        if (kt + 1 < nT) issueKV(kt + 1);

        const uint32_t* Ks = Ks0 + (kt & 1) * KSTG_WORDS;
        const uint32_t* Vs = Vs0 + (kt & 1) * VSTG_WORDS;

        // S = Q @ K^T  (16 x 64 per warp)
        float sacc[8][4];
#pragma unroll
        for (int j = 0; j < 8; j++)
#pragma unroll
            for (int r = 0; r < 4; r++) sacc[j][r] = 0.f;

#pragma unroll
        for (int kf = 0; kf < 8; kf++) {
#pragma unroll
            for (int j = 0; j < 8; j++) {
                uint32_t bfr[2];
                bfr[0] = Ks[(j * 8 + gid) * PADW + kf * 8 + tig];
                bfr[1] = Ks[(j * 8 + gid) * PADW + kf * 8 + tig + 4];
                mma8(sacc[j], qa[kf], bfr);
            }
        }

        // Online softmax per row-half (row gid and gid+8)
#pragma unroll
        for (int hf = 0; hf < 2; hf++) {
            float tmax = -1e30f;
#pragma unroll
            for (int j = 0; j < 8; j++)
                tmax = fmaxf(tmax, fmaxf(sacc[j][2 * hf], sacc[j][2 * hf + 1]));
            tmax = fmaxf(tmax, __shfl_xor_sync(0xffffffffu, tmax, 1));
            tmax = fmaxf(tmax, __shfl_xor_sync(0xffffffffu, tmax, 2));

            float newm = fmaxf(mrow[hf], tmax);
            float corr = __expf(mrow[hf] - newm);
            mrow[hf] = newm;

            float rs = 0.f;
            int rloc = rb + gid + hf * 8;
#pragma unroll
            for (int j = 0; j < 8; j++) {
                float p0 = __expf(sacc[j][2 * hf]     - newm);
                float p1 = __expf(sacc[j][2 * hf + 1] - newm);
                rs += p0 + p1;
                Qs[rloc * PADW + j * 8 + 2 * tig]     = f2tf32(p0);
                Qs[rloc * PADW + j * 8 + 2 * tig + 1] = f2tf32(p1);
                oacc[j][2 * hf]     *= corr;
                oacc[j][2 * hf + 1] *= corr;
            }
            rs += __shfl_xor_sync(0xffffffffu, rs, 1);
            rs += __shfl_xor_sync(0xffffffffu, rs, 2);
            lrow[hf] = lrow[hf] * corr + rs;
        }
        __syncwarp();  // P (per-warp rows) visible to whole warp

        // O += P @ V
#pragma unroll
        for (int kf = 0; kf < 8; kf++) {
            uint32_t af[4];
            af[0] = Qs[(rb + gid    ) * PADW + kf * 8 + tig];
            af[1] = Qs[(rb + gid + 8) * PADW + kf * 8 + tig];
            af[2] = Qs[(rb + gid    ) * PADW + kf * 8 + tig + 4];
            af[3] = Qs[(rb + gid + 8) * PADW + kf * 8 + tig + 4];
#pragma unroll
            for (int j = 0; j < 8; j++) {
                uint32_t bfr[2];
                bfr[0] = Vs[(kf * 8 + tig    ) * PADV + j * 8 + gid];
                bfr[1] = Vs[(kf * 8 + tig + 4) * PADV + j * 8 + gid];
                mma8(oacc[j], af, bfr);
            }
        }
    }

    // Epilogue: normalize and write ctx (tf32-rounded) in (s, b, e) layout
    const int b = n >> 4;   // HEADS = 16
    const int h = n & 15;
#pragma unroll
    for (int hf = 0; hf < 2; hf++) {
        float inv = 1.f / lrow[hf];
        int sg = qt * QROWS + rb + gid + hf * 8;
        size_t rowoff = ((size_t)sg * BATCH + b) * EMB + h * HDIM;
#pragma unroll
        for (int j = 0; j < 8; j++) {
            g_ctx[rowoff + j * 8 + 2 * tig]     =
                __uint_as_float(f2tf32(oacc[j][2 * hf]     * inv));
            g_ctx[rowoff + j * 8 + 2 * tig + 1] =
                __uint_as_float(f2tf32(oacc[j][2 * hf + 1] * inv));
        }
    }
}

// ---------------------------------------------------------------------------
// kernel_launch
// ---------------------------------------------------------------------------
extern "C" void kernel_launch(void* const* d_in, const int* in_sizes, int n_in,
                              void* d_out, int out_size)
{
    (void)in_sizes; (void)n_in; (void)out_size;
    const float* query = (const float*)d_in[0];
    const float* w_in  = (const float*)d_in[1];
    const float* b_in  = (const float*)d_in[2];
    const float* w_out = (const float*)d_in[3];
    const float* b_out = (const float*)d_in[4];
    float* out = (float*)d_out;

    float *qt_p, *wi_p, *wo_p, *ctx_p;
    cudaGetSymbolAddress((void**)&qt_p,  g_qt);
    cudaGetSymbolAddress((void**)&wi_p,  g_wi);
    cudaGetSymbolAddress((void**)&wo_p,  g_wo);
    cudaGetSymbolAddress((void**)&ctx_p, g_ctx);

    // 0) One-time tf32 conversions (pure bandwidth, ~50MB)
    conv_tf32<<<(MROWS * EMB / 4 + 255) / 256, 256>>>(query, qt_p, MROWS * EMB / 4);
    conv_tf32<<<(3 * EMB * EMB / 4 + 255) / 256, 256>>>(w_in, wi_p, 3 * EMB * EMB / 4);
    conv_tf32<<<(EMB * EMB / 4 + 255) / 256, 256>>>(w_out, wo_p, EMB * EMB / 4);

    const int gemm_sh = NSTAGE * STAGE_WORDS * 4;  // 110592 B
    cudaFuncSetAttribute(gemm_tf32<1>, cudaFuncAttributeMaxDynamicSharedMemorySize, gemm_sh);
    cudaFuncSetAttribute(gemm_tf32<0>, cudaFuncAttributeMaxDynamicSharedMemorySize, gemm_sh);

    // 1) QKV projection: (8192 x 1024) @ (3072 x 1024)^T -> scattered q/k/v
    gemm_tf32<1><<<dim3(3072 / 128, 8192 / 128), 256, gemm_sh>>>(
        qt_p, wi_p, b_in, nullptr, MROWS, 3 * EMB, EMB);

    // 2) Flash attention: 64 heads x 16 query tiles of 128
    const int attn_sh = (QROWS * PADW + 2 * KSTG_WORDS + 2 * VSTG_WORDS) * 4;  // 106496 B
    cudaFuncSetAttribute(attn_kernel, cudaFuncAttributeMaxDynamicSharedMemorySize, attn_sh);
    attn_kernel<<<dim3(SEQ / QROWS, NHEAD), 256, attn_sh>>>();

    // 3) Out projection: ctx (8192 x 1024) @ (1024 x 1024)^T + bias -> out
    gemm_tf32<0><<<dim3(1024 / 128, 8192 / 128), 256, gemm_sh>>>(
        ctx_p, wo_p, b_out, out, MROWS, EMB, EMB);
}

// round 6
// speedup vs baseline: 3.0742x; 1.7812x over previous
#include <cuda_runtime.h>
#include <cuda_fp16.h>
#include <cstdint>

// Problem constants
#define SEQ   2048
#define BATCH 4
#define EMB   1024
#define HEADS 16
#define HDIM  64
#define NHEAD (BATCH*HEADS)     // 64
#define MROWS (SEQ*BATCH)       // 8192

// Scratch (device globals — no runtime allocation)
__device__ __align__(16) __half g_q [(size_t)NHEAD * SEQ * HDIM];  // [n][s][d], pre-scaled
__device__ __align__(16) __half g_k [(size_t)NHEAD * SEQ * HDIM];  // [n][s][d]
__device__ __align__(16) __half g_vt[(size_t)NHEAD * HDIM * SEQ];  // [n][d][s]  (transposed)
__device__ __align__(16) __half g_ctx[(size_t)MROWS * EMB];        // (s,b,e)
__device__ __align__(16) __half g_qt[(size_t)MROWS * EMB];         // query, half
__device__ __align__(16) __half g_wi[(size_t)3 * EMB * EMB];       // in_proj_weight, half
__device__ __align__(16) __half g_wo[(size_t)EMB * EMB];           // out_proj_weight, half

// ---------------------------------------------------------------------------
// Helpers
// ---------------------------------------------------------------------------
__device__ __forceinline__ void mma16(float* c, const uint32_t* a, const uint32_t* b) {
    asm volatile(
        "mma.sync.aligned.m16n8k16.row.col.f32.f16.f16.f32 "
        "{%0,%1,%2,%3}, {%4,%5,%6,%7}, {%8,%9}, {%0,%1,%2,%3};\n"
        : "+f"(c[0]), "+f"(c[1]), "+f"(c[2]), "+f"(c[3])
        : "r"(a[0]), "r"(a[1]), "r"(a[2]), "r"(a[3]), "r"(b[0]), "r"(b[1]));
}

__device__ __forceinline__ uint32_t smem_u32(const void* p) {
    uint32_t a;
    asm("{ .reg .u64 t; cvta.to.shared.u64 t, %1; cvt.u32.u64 %0, t; }" : "=r"(a) : "l"(p));
    return a;
}

__device__ __forceinline__ void cp16(uint32_t dst, const void* src) {
    asm volatile("cp.async.cg.shared.global [%0], [%1], 16;" :: "r"(dst), "l"(src));
}
__device__ __forceinline__ void cp_commit() {
    asm volatile("cp.async.commit_group;");
}

__device__ __forceinline__ uint32_t f2h2(float lo, float hi) {
    __half2 h = __floats2half2_rn(lo, hi);
    return *(uint32_t*)&h;
}

// ---------------------------------------------------------------------------
// Elementwise fp32 -> fp16
// ---------------------------------------------------------------------------
__global__ void __launch_bounds__(256) conv_h(const float* __restrict__ src,
                                              __half* __restrict__ dst, int n4)
{
    int i = blockIdx.x * blockDim.x + threadIdx.x;
    if (i < n4) {
        float4 v = ((const float4*)src)[i];
        __half2* d2 = (__half2*)dst;
        d2[2 * i]     = __floats2half2_rn(v.x, v.y);
        d2[2 * i + 1] = __floats2half2_rn(v.z, v.w);
    }
}

// ---------------------------------------------------------------------------
// FP16 GEMM (fp32 accum): C[M,N] = A[M,K] @ W[N,K]^T + bias
// Block 128x128, BK=64, 256 threads (8 warps 2x4, warp tile 64x32).
// 3-stage cp.async pipeline. Smem rows = 32 half2 + pad 4 (stride 36 == 4 mod
// 32): fragment LDS banks = 4*gid + tig, conflict-free.
// MODE 0: fp32 store + bias. MODE 1: qkv scatter (q scaled, V transposed).
// ---------------------------------------------------------------------------
#define GP2 36                         // row stride in half2 units
#define ABYTES_G (128 * GP2 * 4)       // 18432 B per matrix per stage
#define STGB     (2 * ABYTES_G)        // 36864
#define NST      3
#define GEMM_SMEM (NST * STGB)         // 110592

__device__ __forceinline__ void store_qkv(int m, int f, float v, const float* bias) {
    v += bias[f];
    int s = m >> 2;          // BATCH = 4
    int b = m & 3;
    int which = f >> 10;     // EMB = 1024
    int e = f & 1023;
    int h = e >> 6;          // HDIM = 64
    int d = e & 63;
    int n = b * HEADS + h;
    if (which == 0)      g_q [((size_t)n * SEQ + s) * HDIM + d] = __float2half_rn(v * 0.125f);
    else if (which == 1) g_k [((size_t)n * SEQ + s) * HDIM + d] = __float2half_rn(v);
    else                 g_vt[((size_t)n * HDIM + d) * SEQ + s] = __float2half_rn(v);
}

template <int MODE>
__global__ void __launch_bounds__(256, 2) gemm_h(
    const __half* __restrict__ A, const __half* __restrict__ W,
    const float* __restrict__ bias, float* __restrict__ C,
    int M, int N, int K)
{
    extern __shared__ uint32_t sh[];

    const int tid  = threadIdx.x;
    const int warp = tid >> 5;
    const int lane = tid & 31;
    const int gid  = lane >> 2;   // 0..7
    const int tig  = lane & 3;    // 0..3
    const int wm   = warp >> 2;   // 0..1
    const int wn   = warp & 3;    // 0..3

    const int bm = blockIdx.y * 128;
    const int bn = blockIdx.x * 128;

    const int lr = tid >> 3;        // 0..31
    const int lcb = (tid & 7) * 16; // byte col 0..112 (8 halves each)

    uint32_t base = smem_u32(sh);
    uint32_t a_dst0 = base + lr * (GP2 * 4) + lcb;
    uint32_t b_dst0 = a_dst0 + ABYTES_G;

    const __half* a_src = A + (size_t)(bm + lr) * K + (tid & 7) * 8;
    const __half* w_src = W + (size_t)(bn + lr) * K + (tid & 7) * 8;

    const int nT = K / 64;

    auto issue = [&](int t) {
        uint32_t soff = (uint32_t)(t % NST) * STGB;
        int k0 = t * 64;
#pragma unroll
        for (int i = 0; i < 4; i++)
            cp16(a_dst0 + soff + i * 32 * GP2 * 4, a_src + (size_t)i * 32 * K + k0);
#pragma unroll
        for (int i = 0; i < 4; i++)
            cp16(b_dst0 + soff + i * 32 * GP2 * 4, w_src + (size_t)i * 32 * K + k0);
        cp_commit();
    };

    float acc[4][4][4];
#pragma unroll
    for (int i = 0; i < 4; i++)
#pragma unroll
        for (int j = 0; j < 4; j++)
#pragma unroll
            for (int r = 0; r < 4; r++) acc[i][j][r] = 0.f;

    issue(0);
    issue(1);

    for (int t = 0; t < nT; t++) {
        if (t < nT - 1) asm volatile("cp.async.wait_group 1;");
        else            asm volatile("cp.async.wait_group 0;");
        __syncthreads();
        if (t + 2 < nT) issue(t + 2);

        const uint32_t* As = sh + (t % NST) * (STGB / 4);
        const uint32_t* Bs = As + 128 * GP2;

#pragma unroll
        for (int kk = 0; kk < 4; kk++) {
            uint32_t af[4][4];
            uint32_t bf[4][2];
#pragma unroll
            for (int mi = 0; mi < 4; mi++) {
                int rb = wm * 64 + mi * 16;
                af[mi][0] = As[(rb + gid    ) * GP2 + kk * 8 + tig];
                af[mi][1] = As[(rb + gid + 8) * GP2 + kk * 8 + tig];
                af[mi][2] = As[(rb + gid    ) * GP2 + kk * 8 + tig + 4];
                af[mi][3] = As[(rb + gid + 8) * GP2 + kk * 8 + tig + 4];
            }
#pragma unroll
            for (int ni = 0; ni < 4; ni++) {
                int nb = wn * 32 + ni * 8;
                bf[ni][0] = Bs[(nb + gid) * GP2 + kk * 8 + tig];
                bf[ni][1] = Bs[(nb + gid) * GP2 + kk * 8 + tig + 4];
            }
#pragma unroll
            for (int mi = 0; mi < 4; mi++)
#pragma unroll
                for (int ni = 0; ni < 4; ni++)
                    mma16(acc[mi][ni], af[mi], bf[ni]);
        }
    }

    // Epilogue
#pragma unroll
    for (int mi = 0; mi < 4; mi++) {
#pragma unroll
        for (int ni = 0; ni < 4; ni++) {
            int r = bm + wm * 64 + mi * 16 + gid;
            int c = bn + wn * 32 + ni * 8 + 2 * tig;
            if (MODE == 0) {
                float b0 = bias[c], b1 = bias[c + 1];
                C[(size_t)r * N + c]           = acc[mi][ni][0] + b0;
                C[(size_t)r * N + c + 1]       = acc[mi][ni][1] + b1;
                C[(size_t)(r + 8) * N + c]     = acc[mi][ni][2] + b0;
                C[(size_t)(r + 8) * N + c + 1] = acc[mi][ni][3] + b1;
            } else {
                store_qkv(r,     c,     acc[mi][ni][0], bias);
                store_qkv(r,     c + 1, acc[mi][ni][1], bias);
                store_qkv(r + 8, c,     acc[mi][ni][2], bias);
                store_qkv(r + 8, c + 1, acc[mi][ni][3], bias);
            }
        }
    }
}

// ---------------------------------------------------------------------------
// Flash attention, fp16 operands / fp32 accum. One block = (head, 128 queries),
// 256 threads, 8 warps x 16 rows. K loaded [key][d]; V loaded transposed
// [d][key] (written that way by the QKV epilogue). P stays in registers
// (m16n8k16 S-fragment == PV A-fragment after half2 conversion).
// Smem rows: 32 half2 + pad 4 (stride 36): all fragment loads conflict-free.
// ---------------------------------------------------------------------------
#define QROWS 128
#define AP2 36
#define QWORDS (QROWS * AP2)
#define TWORDS (64 * AP2)      // one K or V tile stage

__global__ void __launch_bounds__(256, 2) attn_kernel()
{
    extern __shared__ uint32_t sh[];
    uint32_t* Qs  = sh;                    // QROWS x AP2
    uint32_t* Ks0 = sh + QWORDS;           // 2 stages x 64 x AP2
    uint32_t* Vs0 = Ks0 + 2 * TWORDS;      // 2 stages x 64 x AP2

    const int qt   = blockIdx.x;
    const int n    = blockIdx.y;
    const int tid  = threadIdx.x;
    const int warp = tid >> 5;
    const int lane = tid & 31;
    const int gid  = lane >> 2;
    const int tig  = lane & 3;
    const int rb   = warp * 16;

    const __half* qptr   = g_q  + ((size_t)n * SEQ + qt * QROWS) * HDIM;
    const __half* kbase  = g_k  + (size_t)n * SEQ * HDIM;
    const __half* vtbase = g_vt + (size_t)n * HDIM * SEQ;

    const int lr  = tid >> 3;        // 0..31
    const int lcb = (tid & 7) * 16;  // byte col (8 halves)

    uint32_t base   = smem_u32(sh);
    uint32_t q_dst0 = base + lr * (AP2 * 4) + lcb;
    uint32_t k_dst0 = base + QWORDS * 4 + lr * (AP2 * 4) + lcb;
    uint32_t v_dst0 = base + (QWORDS + 2 * TWORDS) * 4 + lr * (AP2 * 4) + lcb;

    auto issueKV = [&](int kt) {
        uint32_t soff = (uint32_t)(kt & 1) * TWORDS * 4;
#pragma unroll
        for (int i = 0; i < 2; i++) {
            int r = lr + i * 32;
            cp16(k_dst0 + soff + i * 32 * AP2 * 4,
                 kbase + (size_t)(kt * 64 + r) * HDIM + (tid & 7) * 8);
            cp16(v_dst0 + soff + i * 32 * AP2 * 4,
                 vtbase + (size_t)r * SEQ + kt * 64 + (tid & 7) * 8);
        }
        cp_commit();
    };

    // Q tile via cp.async too (4 groups of 32 rows)
#pragma unroll
    for (int i = 0; i < 4; i++)
        cp16(q_dst0 + i * 32 * AP2 * 4,
             qptr + (size_t)(lr + i * 32) * HDIM + (tid & 7) * 8);
    cp_commit();
    issueKV(0);

    asm volatile("cp.async.wait_group 1;");   // Q ready
    __syncthreads();

    // Q fragments: 4 k16 chunks over D=64
    uint32_t qa[4][4];
#pragma unroll
    for (int kf = 0; kf < 4; kf++) {
        qa[kf][0] = Qs[(rb + gid    ) * AP2 + kf * 8 + tig];
        qa[kf][1] = Qs[(rb + gid + 8) * AP2 + kf * 8 + tig];
        qa[kf][2] = Qs[(rb + gid    ) * AP2 + kf * 8 + tig + 4];
        qa[kf][3] = Qs[(rb + gid + 8) * AP2 + kf * 8 + tig + 4];
    }

    float mrow[2] = {-1e30f, -1e30f};
    float lrow[2] = {0.f, 0.f};
    float oacc[8][4];
#pragma unroll
    for (int j = 0; j < 8; j++)
#pragma unroll
        for (int r = 0; r < 4; r++) oacc[j][r] = 0.f;

    const int nT = SEQ / 64;
    for (int kt = 0; kt < nT; kt++) {
        asm volatile("cp.async.wait_group 0;");
        __syncthreads();
        if (kt + 1 < nT) issueKV(kt + 1);

        const uint32_t* Ks = Ks0 + (kt & 1) * TWORDS;
        const uint32_t* Vs = Vs0 + (kt & 1) * TWORDS;

        // S = Q @ K^T  (16 x 64 per warp)
        float sacc[8][4];
#pragma unroll
        for (int j = 0; j < 8; j++)
#pragma unroll
            for (int r = 0; r < 4; r++) sacc[j][r] = 0.f;

#pragma unroll
        for (int kf = 0; kf < 4; kf++) {
#pragma unroll
            for (int j = 0; j < 8; j++) {
                uint32_t bfr[2];
                bfr[0] = Ks[(j * 8 + gid) * AP2 + kf * 8 + tig];
                bfr[1] = Ks[(j * 8 + gid) * AP2 + kf * 8 + tig + 4];
                mma16(sacc[j], qa[kf], bfr);
            }
        }

        // Online softmax; P -> half2 fragments in registers
        uint32_t ph[8][2];
#pragma unroll
        for (int hf = 0; hf < 2; hf++) {
            float tmax = -1e30f;
#pragma unroll
            for (int j = 0; j < 8; j++)
                tmax = fmaxf(tmax, fmaxf(sacc[j][2 * hf], sacc[j][2 * hf + 1]));
            tmax = fmaxf(tmax, __shfl_xor_sync(0xffffffffu, tmax, 1));
            tmax = fmaxf(tmax, __shfl_xor_sync(0xffffffffu, tmax, 2));

            float newm = fmaxf(mrow[hf], tmax);
            float corr = __expf(mrow[hf] - newm);
            mrow[hf] = newm;

            float rs = 0.f;
#pragma unroll
            for (int j = 0; j < 8; j++) {
                float p0 = __expf(sacc[j][2 * hf]     - newm);
                float p1 = __expf(sacc[j][2 * hf + 1] - newm);
                rs += p0 + p1;
                ph[j][hf] = f2h2(p0, p1);
                oacc[j][2 * hf]     *= corr;
                oacc[j][2 * hf + 1] *= corr;
            }
            rs += __shfl_xor_sync(0xffffffffu, rs, 1);
            rs += __shfl_xor_sync(0xffffffffu, rs, 2);
            lrow[hf] = lrow[hf] * corr + rs;
        }

        // O += P @ V  (keys in 4 k16 chunks; A-frags straight from ph)
#pragma unroll
        for (int kf = 0; kf < 4; kf++) {
            uint32_t af[4] = { ph[2 * kf][0], ph[2 * kf][1],
                               ph[2 * kf + 1][0], ph[2 * kf + 1][1] };
#pragma unroll
            for (int j = 0; j < 8; j++) {
                uint32_t bfr[2];
                bfr[0] = Vs[(j * 8 + gid) * AP2 + kf * 8 + tig];
                bfr[1] = Vs[(j * 8 + gid) * AP2 + kf * 8 + tig + 4];
                mma16(oacc[j], af, bfr);
            }
        }
    }

    // Epilogue: normalize, write ctx (half) in (s, b, e) layout
    const int b = n >> 4;   // HEADS = 16
    const int h = n & 15;
#pragma unroll
    for (int hf = 0; hf < 2; hf++) {
        float inv = 1.f / lrow[hf];
        int sg = qt * QROWS + rb + gid + hf * 8;
        size_t rowoff = ((size_t)sg * BATCH + b) * EMB + h * HDIM;
#pragma unroll
        for (int j = 0; j < 8; j++) {
            __half2 o = __floats2half2_rn(oacc[j][2 * hf] * inv,
                                          oacc[j][2 * hf + 1] * inv);
            *(__half2*)&g_ctx[rowoff + j * 8 + 2 * tig] = o;
        }
    }
}

// ---------------------------------------------------------------------------
// kernel_launch
// ---------------------------------------------------------------------------
extern "C" void kernel_launch(void* const* d_in, const int* in_sizes, int n_in,
                              void* d_out, int out_size)
{
    (void)in_sizes; (void)n_in; (void)out_size;
    const float* query = (const float*)d_in[0];
    const float* w_in  = (const float*)d_in[1];
    const float* b_in  = (const float*)d_in[2];
    const float* w_out = (const float*)d_in[3];
    const float* b_out = (const float*)d_in[4];
    float* out = (float*)d_out;

    __half *qt_p, *wi_p, *wo_p, *ctx_p;
    cudaGetSymbolAddress((void**)&qt_p,  g_qt);
    cudaGetSymbolAddress((void**)&wi_p,  g_wi);
    cudaGetSymbolAddress((void**)&wo_p,  g_wo);
    cudaGetSymbolAddress((void**)&ctx_p, g_ctx);

    // 0) fp32 -> fp16 conversions (pure bandwidth)
    conv_h<<<(MROWS * EMB / 4 + 255) / 256, 256>>>(query, qt_p, MROWS * EMB / 4);
    conv_h<<<(3 * EMB * EMB / 4 + 255) / 256, 256>>>(w_in, wi_p, 3 * EMB * EMB / 4);
    conv_h<<<(EMB * EMB / 4 + 255) / 256, 256>>>(w_out, wo_p, EMB * EMB / 4);

    cudaFuncSetAttribute(gemm_h<1>, cudaFuncAttributeMaxDynamicSharedMemorySize, GEMM_SMEM);
    cudaFuncSetAttribute(gemm_h<0>, cudaFuncAttributeMaxDynamicSharedMemorySize, GEMM_SMEM);

    // 1) QKV projection: (8192 x 1024) @ (3072 x 1024)^T -> scattered q/k/vt
    gemm_h<1><<<dim3(3 * EMB / 128, MROWS / 128), 256, GEMM_SMEM>>>(
        qt_p, wi_p, b_in, nullptr, MROWS, 3 * EMB, EMB);

    // 2) Flash attention: 64 heads x 16 query tiles of 128
    const int attn_sh = (QWORDS + 4 * TWORDS) * 4;  // 55296 B
    cudaFuncSetAttribute(attn_kernel, cudaFuncAttributeMaxDynamicSharedMemorySize, attn_sh);
    attn_kernel<<<dim3(SEQ / QROWS, NHEAD), 256, attn_sh>>>();

    // 3) Out projection: ctx (8192 x 1024) @ (1024 x 1024)^T + bias -> out
    gemm_h<0><<<dim3(EMB / 128, MROWS / 128), 256, GEMM_SMEM>>>(
        ctx_p, wo_p, b_out, out, MROWS, EMB, EMB);
}

// round 7
// speedup vs baseline: 3.3074x; 1.0759x over previous
#include <cuda_runtime.h>
#include <cuda_fp16.h>
#include <cstdint>

// Problem constants
#define SEQ   2048
#define BATCH 4
#define EMB   1024
#define HEADS 16
#define HDIM  64
#define NHEAD (BATCH*HEADS)     // 64
#define MROWS (SEQ*BATCH)       // 8192

// Scratch (device globals — no runtime allocation)
__device__ __align__(16) __half g_q [(size_t)NHEAD * SEQ * HDIM];  // [n][s][d], pre-scaled
__device__ __align__(16) __half g_k [(size_t)NHEAD * SEQ * HDIM];  // [n][s][d]
__device__ __align__(16) __half g_vt[(size_t)NHEAD * HDIM * SEQ];  // [n][d][s]  (transposed)
__device__ __align__(16) __half g_ctx[(size_t)MROWS * EMB];        // (s,b,e)
__device__ __align__(16) __half g_qt[(size_t)MROWS * EMB];         // query, half
__device__ __align__(16) __half g_wi[(size_t)3 * EMB * EMB];       // in_proj_weight, half
__device__ __align__(16) __half g_wo[(size_t)EMB * EMB];           // out_proj_weight, half

// ---------------------------------------------------------------------------
// Helpers
// ---------------------------------------------------------------------------
__device__ __forceinline__ void mma16(float* c, const uint32_t* a, const uint32_t* b) {
    asm volatile(
        "mma.sync.aligned.m16n8k16.row.col.f32.f16.f16.f32 "
        "{%0,%1,%2,%3}, {%4,%5,%6,%7}, {%8,%9}, {%0,%1,%2,%3};\n"
        : "+f"(c[0]), "+f"(c[1]), "+f"(c[2]), "+f"(c[3])
        : "r"(a[0]), "r"(a[1]), "r"(a[2]), "r"(a[3]), "r"(b[0]), "r"(b[1]));
}

__device__ __forceinline__ void ldsm4(uint32_t& r0, uint32_t& r1,
                                      uint32_t& r2, uint32_t& r3, uint32_t addr) {
    asm volatile("ldmatrix.sync.aligned.m8n8.x4.shared.b16 {%0,%1,%2,%3}, [%4];"
                 : "=r"(r0), "=r"(r1), "=r"(r2), "=r"(r3) : "r"(addr));
}

__device__ __forceinline__ uint32_t smem_u32(const void* p) {
    uint32_t a;
    asm("{ .reg .u64 t; cvta.to.shared.u64 t, %1; cvt.u32.u64 %0, t; }" : "=r"(a) : "l"(p));
    return a;
}

__device__ __forceinline__ void cp16(uint32_t dst, const void* src) {
    asm volatile("cp.async.cg.shared.global [%0], [%1], 16;" :: "r"(dst), "l"(src));
}
__device__ __forceinline__ void cp_commit() {
    asm volatile("cp.async.commit_group;");
}

__device__ __forceinline__ uint32_t f2h2(float lo, float hi) {
    __half2 h = __floats2half2_rn(lo, hi);
    return *(uint32_t*)&h;
}

// ---------------------------------------------------------------------------
// Elementwise fp32 -> fp16
// ---------------------------------------------------------------------------
__global__ void __launch_bounds__(256) conv_h(const float* __restrict__ src,
                                              __half* __restrict__ dst, int n4)
{
    int i = blockIdx.x * blockDim.x + threadIdx.x;
    if (i < n4) {
        float4 v = ((const float4*)src)[i];
        __half2* d2 = (__half2*)dst;
        d2[2 * i]     = __floats2half2_rn(v.x, v.y);
        d2[2 * i + 1] = __floats2half2_rn(v.z, v.w);
    }
}

// ---------------------------------------------------------------------------
// FP16 GEMM (fp32 accum): C[M,N] = A[M,K] @ W[N,K]^T + bias
// Block 128x128, BK=64, 256 threads (8 warps 2x4, warp tile 64x32).
// 3-stage cp.async pipeline. Fragments via ldmatrix.x4 (6 LDSM per kk step).
// Smem row stride 36 words (==4 mod 32): LDSM phases conflict-free.
// MODE 0: fp32 store + bias. MODE 1: qkv scatter (q scaled, V transposed).
// ---------------------------------------------------------------------------
#define GP2 36                         // row stride in 4B words
#define ABYTES_G (128 * GP2 * 4)       // 18432 B per matrix per stage
#define STGB     (2 * ABYTES_G)        // 36864
#define NST      3
#define GEMM_SMEM (NST * STGB)         // 110592

__device__ __forceinline__ void store_qkv(int m, int f, float v, const float* bias) {
    v += bias[f];
    int s = m >> 2;          // BATCH = 4
    int b = m & 3;
    int which = f >> 10;     // EMB = 1024
    int e = f & 1023;
    int h = e >> 6;          // HDIM = 64
    int d = e & 63;
    int n = b * HEADS + h;
    if (which == 0)      g_q [((size_t)n * SEQ + s) * HDIM + d] = __float2half_rn(v * 0.125f);
    else if (which == 1) g_k [((size_t)n * SEQ + s) * HDIM + d] = __float2half_rn(v);
    else                 g_vt[((size_t)n * HDIM + d) * SEQ + s] = __float2half_rn(v);
}

template <int MODE>
__global__ void __launch_bounds__(256, 2) gemm_h(
    const __half* __restrict__ A, const __half* __restrict__ W,
    const float* __restrict__ bias, float* __restrict__ C,
    int M, int N, int K)
{
    extern __shared__ uint32_t sh[];

    const int tid  = threadIdx.x;
    const int warp = tid >> 5;
    const int lane = tid & 31;
    const int gid  = lane >> 2;   // 0..7
    const int tig  = lane & 3;    // 0..3
    const int wm   = warp >> 2;   // 0..1
    const int wn   = warp & 3;    // 0..3

    // ldmatrix lane decomposition
    const int lr8 = lane & 7;     // row within 8x8 matrix
    const int lm  = lane >> 3;    // matrix index 0..3
    const int a_r = lr8 + (lm & 1) * 8;   // A: matrices (rlo,rhi) x (klo,khi)
    const int a_c = (lm >> 1) * 4;
    const int b_r = lr8 + (lm >> 1) * 8;  // B: matrices (nlo klo, nlo khi, nhi klo, nhi khi)
    const int b_c = (lm & 1) * 4;

    const int bm = blockIdx.y * 128;
    const int bn = blockIdx.x * 128;

    const int lr  = tid >> 3;        // 0..31
    const int lcb = (tid & 7) * 16;  // byte col (8 halves)

    uint32_t base = smem_u32(sh);
    uint32_t a_dst0 = base + lr * (GP2 * 4) + lcb;
    uint32_t b_dst0 = a_dst0 + ABYTES_G;

    const __half* a_src = A + (size_t)(bm + lr) * K + (tid & 7) * 8;
    const __half* w_src = W + (size_t)(bn + lr) * K + (tid & 7) * 8;

    const int nT = K / 64;

    auto issue = [&](int t) {
        uint32_t soff = (uint32_t)(t % NST) * STGB;
        int k0 = t * 64;
#pragma unroll
        for (int i = 0; i < 4; i++)
            cp16(a_dst0 + soff + i * 32 * GP2 * 4, a_src + (size_t)i * 32 * K + k0);
#pragma unroll
        for (int i = 0; i < 4; i++)
            cp16(b_dst0 + soff + i * 32 * GP2 * 4, w_src + (size_t)i * 32 * K + k0);
        cp_commit();
    };

    float acc[4][4][4];
#pragma unroll
    for (int i = 0; i < 4; i++)
#pragma unroll
        for (int j = 0; j < 4; j++)
#pragma unroll
            for (int r = 0; r < 4; r++) acc[i][j][r] = 0.f;

    issue(0);
    issue(1);

    for (int t = 0; t < nT; t++) {
        if (t < nT - 1) asm volatile("cp.async.wait_group 1;");
        else            asm volatile("cp.async.wait_group 0;");
        __syncthreads();
        if (t + 2 < nT) issue(t + 2);

        uint32_t As_a = base + (t % NST) * STGB;
        uint32_t Bs_a = As_a + ABYTES_G;

#pragma unroll
        for (int kk = 0; kk < 4; kk++) {
            uint32_t af[4][4];
            uint32_t bf[4][2];
#pragma unroll
            for (int mi = 0; mi < 4; mi++)
                ldsm4(af[mi][0], af[mi][1], af[mi][2], af[mi][3],
                      As_a + ((wm * 64 + mi * 16 + a_r) * GP2 + kk * 8 + a_c) * 4);
#pragma unroll
            for (int g = 0; g < 2; g++)
                ldsm4(bf[2 * g][0], bf[2 * g][1], bf[2 * g + 1][0], bf[2 * g + 1][1],
                      Bs_a + ((wn * 32 + g * 16 + b_r) * GP2 + kk * 8 + b_c) * 4);
#pragma unroll
            for (int mi = 0; mi < 4; mi++)
#pragma unroll
                for (int ni = 0; ni < 4; ni++)
                    mma16(acc[mi][ni], af[mi], bf[ni]);
        }
    }

    // Epilogue
#pragma unroll
    for (int mi = 0; mi < 4; mi++) {
#pragma unroll
        for (int ni = 0; ni < 4; ni++) {
            int r = bm + wm * 64 + mi * 16 + gid;
            int c = bn + wn * 32 + ni * 8 + 2 * tig;
            if (MODE == 0) {
                float b0 = bias[c], b1 = bias[c + 1];
                C[(size_t)r * N + c]           = acc[mi][ni][0] + b0;
                C[(size_t)r * N + c + 1]       = acc[mi][ni][1] + b1;
                C[(size_t)(r + 8) * N + c]     = acc[mi][ni][2] + b0;
                C[(size_t)(r + 8) * N + c + 1] = acc[mi][ni][3] + b1;
            } else {
                store_qkv(r,     c,     acc[mi][ni][0], bias);
                store_qkv(r,     c + 1, acc[mi][ni][1], bias);
                store_qkv(r + 8, c,     acc[mi][ni][2], bias);
                store_qkv(r + 8, c + 1, acc[mi][ni][3], bias);
            }
        }
    }
}

// ---------------------------------------------------------------------------
// Flash attention, fp16 operands / fp32 accum, ldmatrix fragment loads.
// One block = (head, 128 queries), 256 threads, 8 warps x 16 rows.
// K smem [key][d]; V smem [d][key] (from transposed global). P in registers.
// ---------------------------------------------------------------------------
#define QROWS 128
#define AP2 36
#define QWORDS (QROWS * AP2)
#define TWORDS (64 * AP2)      // one K or V tile stage

__global__ void __launch_bounds__(256, 2) attn_kernel()
{
    extern __shared__ uint32_t sh[];

    const int qt   = blockIdx.x;
    const int n    = blockIdx.y;
    const int tid  = threadIdx.x;
    const int warp = tid >> 5;
    const int lane = tid & 31;
    const int gid  = lane >> 2;
    const int tig  = lane & 3;
    const int rb   = warp * 16;

    const int lr8 = lane & 7;
    const int lm  = lane >> 3;
    const int a_r = lr8 + (lm & 1) * 8;
    const int a_c = (lm >> 1) * 4;
    const int b_r = lr8 + (lm >> 1) * 8;
    const int b_c = (lm & 1) * 4;

    const __half* qptr   = g_q  + ((size_t)n * SEQ + qt * QROWS) * HDIM;
    const __half* kbase  = g_k  + (size_t)n * SEQ * HDIM;
    const __half* vtbase = g_vt + (size_t)n * HDIM * SEQ;

    const int lr  = tid >> 3;        // 0..31
    const int lcb = (tid & 7) * 16;  // byte col (8 halves)

    uint32_t base   = smem_u32(sh);
    uint32_t q_dst0 = base + lr * (AP2 * 4) + lcb;
    uint32_t k_dst0 = base + QWORDS * 4 + lr * (AP2 * 4) + lcb;
    uint32_t v_dst0 = base + (QWORDS + 2 * TWORDS) * 4 + lr * (AP2 * 4) + lcb;

    auto issueKV = [&](int kt) {
        uint32_t soff = (uint32_t)(kt & 1) * TWORDS * 4;
#pragma unroll
        for (int i = 0; i < 2; i++) {
            int r = lr + i * 32;
            cp16(k_dst0 + soff + i * 32 * AP2 * 4,
                 kbase + (size_t)(kt * 64 + r) * HDIM + (tid & 7) * 8);
            cp16(v_dst0 + soff + i * 32 * AP2 * 4,
                 vtbase + (size_t)r * SEQ + kt * 64 + (tid & 7) * 8);
        }
        cp_commit();
    };

    // Q tile via cp.async (4 groups of 32 rows)
#pragma unroll
    for (int i = 0; i < 4; i++)
        cp16(q_dst0 + i * 32 * AP2 * 4,
             qptr + (size_t)(lr + i * 32) * HDIM + (tid & 7) * 8);
    cp_commit();
    issueKV(0);

    asm volatile("cp.async.wait_group 1;");   // Q ready
    __syncthreads();

    // Q fragments: 4 k16 chunks over D=64, via ldmatrix
    uint32_t qa[4][4];
#pragma unroll
    for (int kf = 0; kf < 4; kf++)
        ldsm4(qa[kf][0], qa[kf][1], qa[kf][2], qa[kf][3],
              base + ((rb + a_r) * AP2 + kf * 8 + a_c) * 4);

    float mrow[2] = {-1e30f, -1e30f};
    float lrow[2] = {0.f, 0.f};
    float oacc[8][4];
#pragma unroll
    for (int j = 0; j < 8; j++)
#pragma unroll
        for (int r = 0; r < 4; r++) oacc[j][r] = 0.f;

    const int nT = SEQ / 64;
    for (int kt = 0; kt < nT; kt++) {
        asm volatile("cp.async.wait_group 0;");
        __syncthreads();
        if (kt + 1 < nT) issueKV(kt + 1);

        uint32_t k_a = base + (QWORDS + (kt & 1) * TWORDS) * 4;
        uint32_t v_a = base + (QWORDS + (2 + (kt & 1)) * TWORDS) * 4;

        // S = Q @ K^T  (16 x 64 per warp)
        float sacc[8][4];
#pragma unroll
        for (int j = 0; j < 8; j++)
#pragma unroll
            for (int r = 0; r < 4; r++) sacc[j][r] = 0.f;

#pragma unroll
        for (int kf = 0; kf < 4; kf++) {
#pragma unroll
            for (int jg = 0; jg < 4; jg++) {
                uint32_t b0[2], b1[2];
                ldsm4(b0[0], b0[1], b1[0], b1[1],
                      k_a + ((jg * 16 + b_r) * AP2 + kf * 8 + b_c) * 4);
                mma16(sacc[2 * jg],     qa[kf], b0);
                mma16(sacc[2 * jg + 1], qa[kf], b1);
            }
        }

        // Online softmax; P -> half2 fragments in registers
        uint32_t ph[8][2];
#pragma unroll
        for (int hf = 0; hf < 2; hf++) {
            float tmax = -1e30f;
#pragma unroll
            for (int j = 0; j < 8; j++)
                tmax = fmaxf(tmax, fmaxf(sacc[j][2 * hf], sacc[j][2 * hf + 1]));
            tmax = fmaxf(tmax, __shfl_xor_sync(0xffffffffu, tmax, 1));
            tmax = fmaxf(tmax, __shfl_xor_sync(0xffffffffu, tmax, 2));

            float newm = fmaxf(mrow[hf], tmax);
            float corr = __expf(mrow[hf] - newm);
            mrow[hf] = newm;

            float rs = 0.f;
#pragma unroll
            for (int j = 0; j < 8; j++) {
                float p0 = __expf(sacc[j][2 * hf]     - newm);
                float p1 = __expf(sacc[j][2 * hf + 1] - newm);
                rs += p0 + p1;
                ph[j][hf] = f2h2(p0, p1);
                oacc[j][2 * hf]     *= corr;
                oacc[j][2 * hf + 1] *= corr;
            }
            rs += __shfl_xor_sync(0xffffffffu, rs, 1);
            rs += __shfl_xor_sync(0xffffffffu, rs, 2);
            lrow[hf] = lrow[hf] * corr + rs;
        }

        // O += P @ V  (keys in 4 k16 chunks; A-frags straight from ph)
#pragma unroll
        for (int kf = 0; kf < 4; kf++) {
            uint32_t af[4] = { ph[2 * kf][0], ph[2 * kf][1],
                               ph[2 * kf + 1][0], ph[2 * kf + 1][1] };
#pragma unroll
            for (int jg = 0; jg < 4; jg++) {
                uint32_t b0[2], b1[2];
                ldsm4(b0[0], b0[1], b1[0], b1[1],
                      v_a + ((jg * 16 + b_r) * AP2 + kf * 8 + b_c) * 4);
                mma16(oacc[2 * jg],     af, b0);
                mma16(oacc[2 * jg + 1], af, b1);
            }
        }
    }

    // Epilogue: normalize, write ctx (half) in (s, b, e) layout
    const int b = n >> 4;   // HEADS = 16
    const int h = n & 15;
#pragma unroll
    for (int hf = 0; hf < 2; hf++) {
        float inv = 1.f / lrow[hf];
        int sg = qt * QROWS + rb + gid + hf * 8;
        size_t rowoff = ((size_t)sg * BATCH + b) * EMB + h * HDIM;
#pragma unroll
        for (int j = 0; j < 8; j++) {
            __half2 o = __floats2half2_rn(oacc[j][2 * hf] * inv,
                                          oacc[j][2 * hf + 1] * inv);
            *(__half2*)&g_ctx[rowoff + j * 8 + 2 * tig] = o;
        }
    }
}

// ---------------------------------------------------------------------------
// kernel_launch
// ---------------------------------------------------------------------------
extern "C" void kernel_launch(void* const* d_in, const int* in_sizes, int n_in,
                              void* d_out, int out_size)
{
    (void)in_sizes; (void)n_in; (void)out_size;
    const float* query = (const float*)d_in[0];
    const float* w_in  = (const float*)d_in[1];
    const float* b_in  = (const float*)d_in[2];
    const float* w_out = (const float*)d_in[3];
    const float* b_out = (const float*)d_in[4];
    float* out = (float*)d_out;

    __half *qt_p, *wi_p, *wo_p, *ctx_p;
    cudaGetSymbolAddress((void**)&qt_p,  g_qt);
    cudaGetSymbolAddress((void**)&wi_p,  g_wi);
    cudaGetSymbolAddress((void**)&wo_p,  g_wo);
    cudaGetSymbolAddress((void**)&ctx_p, g_ctx);

    // 0) fp32 -> fp16 conversions (pure bandwidth)
    conv_h<<<(MROWS * EMB / 4 + 255) / 256, 256>>>(query, qt_p, MROWS * EMB / 4);
    conv_h<<<(3 * EMB * EMB / 4 + 255) / 256, 256>>>(w_in, wi_p, 3 * EMB * EMB / 4);
    conv_h<<<(EMB * EMB / 4 + 255) / 256, 256>>>(w_out, wo_p, EMB * EMB / 4);

    cudaFuncSetAttribute(gemm_h<1>, cudaFuncAttributeMaxDynamicSharedMemorySize, GEMM_SMEM);
    cudaFuncSetAttribute(gemm_h<0>, cudaFuncAttributeMaxDynamicSharedMemorySize, GEMM_SMEM);

    // 1) QKV projection: (8192 x 1024) @ (3072 x 1024)^T -> scattered q/k/vt
    gemm_h<1><<<dim3(3 * EMB / 128, MROWS / 128), 256, GEMM_SMEM>>>(
        qt_p, wi_p, b_in, nullptr, MROWS, 3 * EMB, EMB);

    // 2) Flash attention: 64 heads x 16 query tiles of 128
    const int attn_sh = (QWORDS + 4 * TWORDS) * 4;  // 55296 B
    cudaFuncSetAttribute(attn_kernel, cudaFuncAttributeMaxDynamicSharedMemorySize, attn_sh);
    attn_kernel<<<dim3(SEQ / QROWS, NHEAD), 256, attn_sh>>>();

    // 3) Out projection: ctx (8192 x 1024) @ (1024 x 1024)^T + bias -> out
    gemm_h<0><<<dim3(EMB / 128, MROWS / 128), 256, GEMM_SMEM>>>(
        ctx_p, wo_p, b_out, out, MROWS, EMB, EMB);
}